// round 8
// baseline (speedup 1.0000x reference)
#include <cuda_runtime.h>
#include <cuda_fp16.h>
#include <cstdint>

#define NB 32768
#define ND 512
#define NC 527
#define NPAD 576     // 3 * 192

#define BM 128
#define BN 192
#define BKH 32          // halfs per K-stage
#define RPAD 40         // padded row stride in halfs (80B; conflict-free LDSM)
#define STAGES 4
#define NIT (ND / BKH)  // 16
#define NRB (NB / BM)   // 256 row blocks

#define A_STAGE_H (BM * RPAD)   // 5120 halfs
#define B_STAGE_H (BN * RPAD)   // 7680 halfs
#define STAGE_H   (A_STAGE_H + B_STAGE_H)
#define SMEM_DYN  (STAGES * STAGE_H * 2)   // 102,400 B

// Scratch: fp16 copies of X and (padded) W, fp32 logits, completion counters.
__device__ __half g_Xh[(size_t)NB * ND];     // 32 MB
__device__ __half g_Wh[(size_t)NPAD * ND];   // 0.56 MB (rows >= NC zeroed)
__device__ float  g_LOG[(size_t)NB * NPAD];  // 75.5 MB
__device__ int    g_cnt[NRB];                // zero-init; returns to 0 each replay

// ---------------------------------------------------------------------------
// K0a: zero outputs (must precede any fused reduce)
// ---------------------------------------------------------------------------
__global__ void k_zero(float* out) {
    if (threadIdx.x < 2) out[threadIdx.x] = 0.0f;
}

// ---------------------------------------------------------------------------
// K0b: fp32 -> fp16 conversion (full tensors, full-grid for max DRAM BW)
// ---------------------------------------------------------------------------
__global__ __launch_bounds__(256)
void k_conv(const float* __restrict__ X, const float* __restrict__ W) {
    const size_t stride = (size_t)gridDim.x * blockDim.x;
    size_t i0 = (size_t)blockIdx.x * blockDim.x + threadIdx.x;

    const float4* X4 = (const float4*)X;
    const size_t nx4 = (size_t)NB * ND / 4;
    for (size_t j = i0; j < nx4; j += stride) {
        float4 v = X4[j];
        __half2 h0 = __floats2half2_rn(v.x, v.y);
        __half2 h1 = __floats2half2_rn(v.z, v.w);
        uint2 p;
        p.x = *(uint32_t*)&h0; p.y = *(uint32_t*)&h1;
        *(uint2*)&g_Xh[j * 4] = p;
    }

    const size_t nw4 = (size_t)NPAD * ND / 4;
    for (size_t j = i0; j < nw4; j += stride) {
        size_t row = j >> 7;            // 128 float4 per 512-col row
        uint2 p = make_uint2(0u, 0u);
        if (row < NC) {
            float4 v = *(const float4*)&W[j * 4];
            __half2 h0 = __floats2half2_rn(v.x, v.y);
            __half2 h1 = __floats2half2_rn(v.z, v.w);
            p.x = *(uint32_t*)&h0; p.y = *(uint32_t*)&h1;
        }
        *(uint2*)&g_Wh[j * 4] = p;
    }
}

__device__ __forceinline__ void mma_f16(float* c, const uint32_t* a, const uint32_t* b) {
    asm volatile(
        "mma.sync.aligned.m16n8k16.row.col.f32.f16.f16.f32 "
        "{%0,%1,%2,%3}, {%4,%5,%6,%7}, {%8,%9}, {%0,%1,%2,%3};\n"
        : "+f"(c[0]), "+f"(c[1]), "+f"(c[2]), "+f"(c[3])
        : "r"(a[0]), "r"(a[1]), "r"(a[2]), "r"(a[3]), "r"(b[0]), "r"(b[1]));
}

__device__ __forceinline__ void ldsm_x4(uint32_t* r, uint32_t addr) {
    asm volatile("ldmatrix.sync.aligned.m8n8.x4.shared.b16 {%0,%1,%2,%3}, [%4];"
                 : "=r"(r[0]), "=r"(r[1]), "=r"(r[2]), "=r"(r[3]) : "r"(addr));
}

// ---------------------------------------------------------------------------
// K1: fused fp16 GEMM + (last CTA of each row block) BCE/top-k reduction.
// GEMM: CTA 128x192, 8 warps (2m x 4n), warp tile 64x48, 4-stage cp.async.
// Reduce: 8 warps x 8 iterations x 2 rows = 128 rows, 2-bit radix select.
// ---------------------------------------------------------------------------
__global__ __launch_bounds__(256, 1)
void k_gemm(const __half* __restrict__ Xh, const __half* __restrict__ Wh,
            const float* __restrict__ bias, const float* __restrict__ Y,
            const float* __restrict__ pw, float* __restrict__ out) {
    extern __shared__ __half smh[];   // [STAGES][A | B], RPAD-padded rows
    __shared__ float sBias[BN];
    __shared__ int sLast;

    const int tid  = threadIdx.x;
    const int lane = tid & 31;
    const int warp = tid >> 5;
    const int wm   = warp & 1;      // 0..1
    const int wn   = warp >> 1;     // 0..3
    const int g    = lane >> 2;     // 0..7
    const int t    = lane & 3;      // 0..3

    const int col0 = blockIdx.x * BN;
    const int rb   = blockIdx.y;
    const int row0 = rb * BM;

    for (int i = tid; i < BN; i += 256)
        sBias[i] = (col0 + i < NC) ? bias[col0 + i] : 0.0f;

    const int aRow = (lane & 7) + ((lane >> 3) & 1) * 8;
    const int aCol = (lane >> 4) * 8;
    const int bRow = (lane & 7) + (lane >> 4) * 8;
    const int bCol = ((lane >> 3) & 1) * 8;

    const uint32_t smBase = (uint32_t)__cvta_generic_to_shared(smh);

    float acc[4][6][4];
    #pragma unroll
    for (int i = 0; i < 4; i++)
        #pragma unroll
        for (int j = 0; j < 6; j++)
            #pragma unroll
            for (int r = 0; r < 4; r++) acc[i][j][r] = 0.0f;

    auto load_stage = [&](int kt, int buf) {
        __half* sA = smh + buf * STAGE_H;
        __half* sB = sA + A_STAGE_H;
        const __half* Xb = Xh + (size_t)row0 * ND + kt * BKH;
        #pragma unroll
        for (int i = 0; i < 2; i++) {              // A: 512 x 16B chunks / 256 thr
            int id = i * 256 + tid;
            int r = id >> 2, c = (id & 3) * 8;
            uint32_t dst = (uint32_t)__cvta_generic_to_shared(&sA[r * RPAD + c]);
            asm volatile("cp.async.ca.shared.global [%0], [%1], 16;\n"
                         :: "r"(dst), "l"(Xb + (size_t)r * ND + c));
        }
        const __half* Wb = Wh + (size_t)col0 * ND + kt * BKH;
        #pragma unroll
        for (int i = 0; i < 3; i++) {              // B: 768 x 16B chunks / 256 thr
            int id = i * 256 + tid;
            int r = id >> 2, c = (id & 3) * 8;
            uint32_t dst = (uint32_t)__cvta_generic_to_shared(&sB[r * RPAD + c]);
            asm volatile("cp.async.ca.shared.global [%0], [%1], 16;\n"
                         :: "r"(dst), "l"(Wb + (size_t)r * ND + c));
        }
    };

    auto compute_stage = [&](int buf) {
        const uint32_t sA = smBase + (buf * STAGE_H) * 2;
        const uint32_t sB = sA + A_STAGE_H * 2;
        #pragma unroll
        for (int ks = 0; ks < 2; ks++) {           // 2 x k16 per BK=32
            const int k0 = ks * 16;
            uint32_t a[4][4], bf[3][4];
            #pragma unroll
            for (int mt = 0; mt < 4; mt++) {
                int r = wm * 64 + mt * 16 + aRow;
                ldsm_x4(a[mt], sA + (r * RPAD + k0 + aCol) * 2);
            }
            #pragma unroll
            for (int nb = 0; nb < 3; nb++) {       // 2 n-tiles per LDSM
                int c = wn * 48 + nb * 16 + bRow;
                ldsm_x4(bf[nb], sB + (c * RPAD + k0 + bCol) * 2);
            }
            #pragma unroll
            for (int mt = 0; mt < 4; mt++)
                #pragma unroll
                for (int nt = 0; nt < 6; nt++)
                    mma_f16(acc[mt][nt], a[mt], &bf[nt >> 1][(nt & 1) * 2]);
        }
    };

    load_stage(0, 0); asm volatile("cp.async.commit_group;\n");
    load_stage(1, 1); asm volatile("cp.async.commit_group;\n");
    load_stage(2, 2); asm volatile("cp.async.commit_group;\n");

    for (int it = 0; it < NIT; it++) {
        asm volatile("cp.async.wait_group 2;\n");
        __syncthreads();
        if (it + 3 < NIT) load_stage(it + 3, (it + 3) & 3);   // prefetch first
        asm volatile("cp.async.commit_group;\n");
        compute_stage(it & 3);
    }

    // epilogue: bias add + store fp32 logits
    #pragma unroll
    for (int mt = 0; mt < 4; mt++) {
        int gr = row0 + wm * 64 + mt * 16 + g;
        #pragma unroll
        for (int nt = 0; nt < 6; nt++) {
            int ci = wn * 48 + nt * 8 + 2 * t;
            float bv0 = sBias[ci], bv1 = sBias[ci + 1];
            int gc = col0 + ci;
            float2 v0 = make_float2(acc[mt][nt][0] + bv0, acc[mt][nt][1] + bv1);
            float2 v1 = make_float2(acc[mt][nt][2] + bv0, acc[mt][nt][3] + bv1);
            *(float2*)&g_LOG[(size_t)(gr    ) * NPAD + gc] = v0;
            *(float2*)&g_LOG[(size_t)(gr + 8) * NPAD + gc] = v1;
        }
    }

    // ---- completion gate: last of the 3 column-tile CTAs reduces the block --
    __threadfence();
    __syncthreads();
    if (tid == 0) sLast = atomicAdd(&g_cnt[rb], 1);
    __syncthreads();
    if (sLast != 2) return;
    __threadfence();   // make peer CTAs' logit stores visible

    float lsumT = 0.0f, scT = 0.0f;

    #pragma unroll 1
    for (int it2 = 0; it2 < 8; it2++) {
        const int rbase = row0 + warp * 16 + it2 * 2;

        unsigned u[2][17];
        unsigned pm[2];
        int      cnt[2];
        float lsum = 0.0f;

        #pragma unroll
        for (int r = 0; r < 2; r++) {
            const float* lg = g_LOG + (size_t)(rbase + r) * NPAD;
            const float* yr = Y + (size_t)(rbase + r) * NC;
            unsigned m = 0;
            #pragma unroll
            for (int i = 0; i < 17; i++) {
                int c = lane + 32 * i;        // max 543 < NPAD: in-bounds
                bool v = (c < NC);
                float z  = lg[c];
                float yy = v ? yr[c] : 0.0f;
                float p  = v ? pw[c] : 0.0f;
                float e  = __expf(-fabsf(z));
                float sp = fmaxf(z, 0.0f) + __logf(1.0f + e);   // softplus(z)
                float w  = 1.0f + yy * (p - 1.0f);
                lsum += v ? (w * sp - p * yy * z) : 0.0f;
                m |= (yy != 0.0f) ? (1u << i) : 0u;
                unsigned bb = __float_as_uint(z);
                unsigned uu = bb ^ (((unsigned)((int)bb >> 31)) | 0x80000000u);
                u[r][i] = v ? uu : 0u;        // 0 sorts below any valid key
            }
            pm[r]  = m;
            cnt[r] = __popc(m);
        }

        {
            int q = cnt[0] | (cnt[1] << 16);
            q = __reduce_add_sync(0xffffffffu, q);
            cnt[0] = q & 0xffff; cnt[1] = q >> 16;
        }
        #pragma unroll
        for (int o = 16; o; o >>= 1) lsum += __shfl_xor_sync(0xffffffffu, lsum, o);

        unsigned pre[2] = {0u, 0u};
        int cur[2] = {0x7fffffff, 0x7fffffff};
        int done = 0;
        #pragma unroll 1
        for (int bit = 30; bit >= 0; bit -= 2) {
            const unsigned m1 = 2u << bit;
            const unsigned m0 = 1u << bit;
            int pk[2];
            #pragma unroll
            for (int r = 0; r < 2; r++) {
                const unsigned cH  = pre[r] | m1;
                const unsigned cHB = cH | m0;
                const unsigned cL  = pre[r] | m0;
                int nH = 0, nHB = 0, nL = 0;
                #pragma unroll
                for (int i = 0; i < 17; i++) {
                    nH  += (u[r][i] >= cH);
                    nHB += (u[r][i] >= cHB);
                    nL  += (u[r][i] >= cL);
                }
                pk[r] = nH | (nHB << 10) | (nL << 20);
            }
            pk[0] = __reduce_add_sync(0xffffffffu, pk[0]);
            pk[1] = __reduce_add_sync(0xffffffffu, pk[1]);
            #pragma unroll
            for (int r = 0; r < 2; r++) {
                int nH  = pk[r] & 1023;
                int nHB = (pk[r] >> 10) & 1023;
                int nL  = (pk[r] >> 20) & 1023;
                if (nHB >= cnt[r])      { pre[r] |= m1 | m0; cur[r] = nHB; }
                else if (nH >= cnt[r])  { pre[r] |= m1;      cur[r] = nH; }
                else if (nL >= cnt[r])  { pre[r] |= m0;      cur[r] = nL; }
                done |= (cur[r] == cnt[r]) << r;
            }
            if (done == 3) break;
        }

        int h0 = 0, h1 = 0;
        #pragma unroll
        for (int i = 0; i < 17; i++) {
            h0 += (((pm[0] >> i) & 1u) && (u[0][i] >= pre[0])) ? 1 : 0;
            h1 += (((pm[1] >> i) & 1u) && (u[1][i] >= pre[1])) ? 1 : 0;
        }
        int hh = h0 | (h1 << 16);
        hh = __reduce_add_sync(0xffffffffu, hh);

        lsumT += lsum;   // identical on all lanes
        scT   += (float)(hh & 0xffff) / (float)cnt[0]
               + (float)(hh >> 16)    / (float)cnt[1];
    }

    if (lane == 0) {
        atomicAdd(&out[0], lsumT * (1.0f / ((float)NB * (float)NC)));
        atomicAdd(&out[1], scT * (1.0f / (float)NB));
    }

    __syncthreads();
    if (tid == 0) g_cnt[rb] = 0;   // reset for next graph replay
}

// ---------------------------------------------------------------------------
// launch: zero -> conv -> fused gemm+reduce (single stream)
// ---------------------------------------------------------------------------
extern "C" void kernel_launch(void* const* d_in, const int* in_sizes, int n_in,
                              void* d_out, int out_size) {
    const float *x = nullptr, *y = nullptr, *W = nullptr, *b = nullptr, *pwt = nullptr;
    int n527 = 0;
    for (int i = 0; i < n_in; i++) {
        if      (in_sizes[i] == NB * ND) x = (const float*)d_in[i];
        else if (in_sizes[i] == NB * NC) y = (const float*)d_in[i];
        else if (in_sizes[i] == NC * ND) W = (const float*)d_in[i];
        else if (in_sizes[i] == NC) {
            if (n527 == 0) b = (const float*)d_in[i];
            else           pwt = (const float*)d_in[i];
            n527++;
        }
    }
    float* out = (float*)d_out;

    static int inited = 0;
    if (!inited) {
        cudaFuncSetAttribute(k_gemm, cudaFuncAttributeMaxDynamicSharedMemorySize, SMEM_DYN);
        inited = 1;
    }

    __half *xh, *wh;
    cudaGetSymbolAddress((void**)&xh, g_Xh);
    cudaGetSymbolAddress((void**)&wh, g_Wh);

    k_zero<<<1, 32>>>(out);
    k_conv<<<2048, 256>>>(x, W);
    dim3 gg(NPAD / BN, NRB);   // (3, 256), x fastest
    k_gemm<<<gg, 256, SMEM_DYN>>>(xh, wh, b, y, pwt, out);
}

// round 9
// speedup vs baseline: 1.1378x; 1.1378x over previous
#include <cuda_runtime.h>
#include <cuda_fp16.h>
#include <cstdint>

#define NB 32768
#define ND 512
#define NC 527
#define NPAD 576     // 3 * 192

#define NCH 2
#define CRB  (NB / BM / NCH)    // 128 row-blocks per chunk
#define CROWS (NB / NCH)        // 16384 rows per chunk

#define BM 128
#define BN 192
#define BKH 32          // halfs per K-stage
#define RPAD 40         // padded row stride in halfs (80B; conflict-free LDSM)
#define STAGES 4
#define NIT (ND / BKH)  // 16

#define A_STAGE_H (BM * RPAD)   // 5120 halfs
#define B_STAGE_H (BN * RPAD)   // 7680 halfs
#define STAGE_H   (A_STAGE_H + B_STAGE_H)
#define SMEM_DYN  (STAGES * STAGE_H * 2)   // 102,400 B

// Scratch: fp16 copies of X and (padded) W, fp32 logits.
__device__ __half g_Xh[(size_t)NB * ND];     // 32 MB
__device__ __half g_Wh[(size_t)NPAD * ND];   // 0.56 MB (rows >= NC zeroed)
__device__ float  g_LOG[(size_t)NB * NPAD];  // 75.5 MB

// ---------------------------------------------------------------------------
// K0: fp32 -> fp16 conversion (full tensors, full grid) + output zeroing
// ---------------------------------------------------------------------------
__global__ __launch_bounds__(256)
void k_conv(const float* __restrict__ X, const float* __restrict__ W,
            float* __restrict__ out) {
    if (blockIdx.x == 0 && threadIdx.x < 2) out[threadIdx.x] = 0.0f;

    const size_t stride = (size_t)gridDim.x * blockDim.x;
    size_t i0 = (size_t)blockIdx.x * blockDim.x + threadIdx.x;

    const float4* X4 = (const float4*)X;
    const size_t nx4 = (size_t)NB * ND / 4;
    for (size_t j = i0; j < nx4; j += stride) {
        float4 v = X4[j];
        __half2 h0 = __floats2half2_rn(v.x, v.y);
        __half2 h1 = __floats2half2_rn(v.z, v.w);
        uint2 p;
        p.x = *(uint32_t*)&h0; p.y = *(uint32_t*)&h1;
        *(uint2*)&g_Xh[j * 4] = p;
    }

    const size_t nw4 = (size_t)NPAD * ND / 4;
    for (size_t j = i0; j < nw4; j += stride) {
        size_t row = j >> 7;            // 128 float4 per 512-col row
        uint2 p = make_uint2(0u, 0u);
        if (row < NC) {
            float4 v = *(const float4*)&W[j * 4];
            __half2 h0 = __floats2half2_rn(v.x, v.y);
            __half2 h1 = __floats2half2_rn(v.z, v.w);
            p.x = *(uint32_t*)&h0; p.y = *(uint32_t*)&h1;
        }
        *(uint2*)&g_Wh[j * 4] = p;
    }
}

__device__ __forceinline__ void mma_f16(float* c, const uint32_t* a, const uint32_t* b) {
    asm volatile(
        "mma.sync.aligned.m16n8k16.row.col.f32.f16.f16.f32 "
        "{%0,%1,%2,%3}, {%4,%5,%6,%7}, {%8,%9}, {%0,%1,%2,%3};\n"
        : "+f"(c[0]), "+f"(c[1]), "+f"(c[2]), "+f"(c[3])
        : "r"(a[0]), "r"(a[1]), "r"(a[2]), "r"(a[3]), "r"(b[0]), "r"(b[1]));
}

__device__ __forceinline__ void ldsm_x4(uint32_t* r, uint32_t addr) {
    asm volatile("ldmatrix.sync.aligned.m8n8.x4.shared.b16 {%0,%1,%2,%3}, [%4];"
                 : "=r"(r[0]), "=r"(r[1]), "=r"(r[2]), "=r"(r[3]) : "r"(addr));
}

// ---------------------------------------------------------------------------
// K1: fp16 mma GEMM for one row chunk (identical core to R6 best kernel)
// ---------------------------------------------------------------------------
__global__ __launch_bounds__(256, 1)
void k_gemm(const __half* __restrict__ Xh, const __half* __restrict__ Wh,
            const float* __restrict__ bias, int rowOff) {
    extern __shared__ __half smh[];   // [STAGES][A | B], RPAD-padded rows
    __shared__ float sBias[BN];

    const int tid  = threadIdx.x;
    const int lane = tid & 31;
    const int warp = tid >> 5;
    const int wm   = warp & 1;      // 0..1
    const int wn   = warp >> 1;     // 0..3
    const int g    = lane >> 2;     // 0..7
    const int t    = lane & 3;      // 0..3

    const int col0 = blockIdx.x * BN;
    const int row0 = rowOff + blockIdx.y * BM;

    for (int i = tid; i < BN; i += 256)
        sBias[i] = (col0 + i < NC) ? bias[col0 + i] : 0.0f;

    const int aRow = (lane & 7) + ((lane >> 3) & 1) * 8;
    const int aCol = (lane >> 4) * 8;
    const int bRow = (lane & 7) + (lane >> 4) * 8;
    const int bCol = ((lane >> 3) & 1) * 8;

    const uint32_t smBase = (uint32_t)__cvta_generic_to_shared(smh);

    float acc[4][6][4];
    #pragma unroll
    for (int i = 0; i < 4; i++)
        #pragma unroll
        for (int j = 0; j < 6; j++)
            #pragma unroll
            for (int r = 0; r < 4; r++) acc[i][j][r] = 0.0f;

    auto load_stage = [&](int kt, int buf) {
        __half* sA = smh + buf * STAGE_H;
        __half* sB = sA + A_STAGE_H;
        const __half* Xb = Xh + (size_t)row0 * ND + kt * BKH;
        #pragma unroll
        for (int i = 0; i < 2; i++) {              // A: 512 x 16B chunks / 256 thr
            int id = i * 256 + tid;
            int r = id >> 2, c = (id & 3) * 8;
            uint32_t dst = (uint32_t)__cvta_generic_to_shared(&sA[r * RPAD + c]);
            asm volatile("cp.async.ca.shared.global [%0], [%1], 16;\n"
                         :: "r"(dst), "l"(Xb + (size_t)r * ND + c));
        }
        const __half* Wb = Wh + (size_t)col0 * ND + kt * BKH;
        #pragma unroll
        for (int i = 0; i < 3; i++) {              // B: 768 x 16B chunks / 256 thr
            int id = i * 256 + tid;
            int r = id >> 2, c = (id & 3) * 8;
            uint32_t dst = (uint32_t)__cvta_generic_to_shared(&sB[r * RPAD + c]);
            asm volatile("cp.async.ca.shared.global [%0], [%1], 16;\n"
                         :: "r"(dst), "l"(Wb + (size_t)r * ND + c));
        }
    };

    auto compute_stage = [&](int buf) {
        const uint32_t sA = smBase + (buf * STAGE_H) * 2;
        const uint32_t sB = sA + A_STAGE_H * 2;
        #pragma unroll
        for (int ks = 0; ks < 2; ks++) {           // 2 x k16 per BK=32
            const int k0 = ks * 16;
            uint32_t a[4][4], bf[3][4];
            #pragma unroll
            for (int mt = 0; mt < 4; mt++) {
                int r = wm * 64 + mt * 16 + aRow;
                ldsm_x4(a[mt], sA + (r * RPAD + k0 + aCol) * 2);
            }
            #pragma unroll
            for (int nb = 0; nb < 3; nb++) {       // 2 n-tiles per LDSM
                int c = wn * 48 + nb * 16 + bRow;
                ldsm_x4(bf[nb], sB + (c * RPAD + k0 + bCol) * 2);
            }
            #pragma unroll
            for (int mt = 0; mt < 4; mt++)
                #pragma unroll
                for (int nt = 0; nt < 6; nt++)
                    mma_f16(acc[mt][nt], a[mt], &bf[nt >> 1][(nt & 1) * 2]);
        }
    };

    load_stage(0, 0); asm volatile("cp.async.commit_group;\n");
    load_stage(1, 1); asm volatile("cp.async.commit_group;\n");
    load_stage(2, 2); asm volatile("cp.async.commit_group;\n");

    for (int it = 0; it < NIT; it++) {
        asm volatile("cp.async.wait_group 2;\n");
        __syncthreads();
        if (it + 3 < NIT) load_stage(it + 3, (it + 3) & 3);   // prefetch first
        asm volatile("cp.async.commit_group;\n");
        compute_stage(it & 3);
    }

    // epilogue: bias add + store fp32 logits
    #pragma unroll
    for (int mt = 0; mt < 4; mt++) {
        int gr = row0 + wm * 64 + mt * 16 + g;
        #pragma unroll
        for (int nt = 0; nt < 6; nt++) {
            int ci = wn * 48 + nt * 8 + 2 * t;
            float bv0 = sBias[ci], bv1 = sBias[ci + 1];
            int gc = col0 + ci;
            float2 v0 = make_float2(acc[mt][nt][0] + bv0, acc[mt][nt][1] + bv1);
            float2 v1 = make_float2(acc[mt][nt][2] + bv0, acc[mt][nt][3] + bv1);
            *(float2*)&g_LOG[(size_t)(gr    ) * NPAD + gc] = v0;
            *(float2*)&g_LOG[(size_t)(gr + 8) * NPAD + gc] = v1;
        }
    }
}

// ---------------------------------------------------------------------------
// K2: per-row BCE loss + exact top-k hit rate, one row chunk.
// One warp handles two rows; 2-bit-per-pass radix select. (R6 core.)
// ---------------------------------------------------------------------------
__global__ __launch_bounds__(256)
void k_reduce(const float* __restrict__ Y, const float* __restrict__ pw,
              float* __restrict__ out, int rowOff) {
    const int warp = threadIdx.x >> 5;
    const int lane = threadIdx.x & 31;
    const int row0 = rowOff + (blockIdx.x * 8 + warp) * 2;

    unsigned u[2][17];
    unsigned pm[2];
    int      cnt[2];
    float lsum = 0.0f;

    #pragma unroll
    for (int r = 0; r < 2; r++) {
        const float* lg = g_LOG + (size_t)(row0 + r) * NPAD;
        const float* yr = Y + (size_t)(row0 + r) * NC;
        unsigned m = 0;
        #pragma unroll
        for (int i = 0; i < 17; i++) {
            int c = lane + 32 * i;        // max 543 < NPAD: logits in-bounds
            bool v = (c < NC);
            float z  = lg[c];
            float yy = v ? yr[c] : 0.0f;
            float p  = v ? pw[c] : 0.0f;
            float e  = __expf(-fabsf(z));
            float sp = fmaxf(z, 0.0f) + __logf(1.0f + e);   // softplus(z)
            float w  = 1.0f + yy * (p - 1.0f);
            lsum += v ? (w * sp - p * yy * z) : 0.0f;
            m |= (yy != 0.0f) ? (1u << i) : 0u;
            unsigned bb = __float_as_uint(z);
            unsigned uu = bb ^ (((unsigned)((int)bb >> 31)) | 0x80000000u);
            u[r][i] = v ? uu : 0u;        // 0 sorts below every valid key
        }
        pm[r]  = m;
        cnt[r] = __popc(m);
    }

    {
        int q = cnt[0] | (cnt[1] << 16);
        q = __reduce_add_sync(0xffffffffu, q);
        cnt[0] = q & 0xffff; cnt[1] = q >> 16;
    }
    #pragma unroll
    for (int o = 16; o; o >>= 1) lsum += __shfl_xor_sync(0xffffffffu, lsum, o);

    unsigned pre[2] = {0u, 0u};
    int cur[2] = {0x7fffffff, 0x7fffffff};
    int done = 0;
    #pragma unroll 1
    for (int bit = 30; bit >= 0; bit -= 2) {
        const unsigned m1 = 2u << bit;
        const unsigned m0 = 1u << bit;
        int pk[2];
        #pragma unroll
        for (int r = 0; r < 2; r++) {
            const unsigned cH  = pre[r] | m1;
            const unsigned cHB = cH | m0;
            const unsigned cL  = pre[r] | m0;
            int nH = 0, nHB = 0, nL = 0;
            #pragma unroll
            for (int i = 0; i < 17; i++) {
                nH  += (u[r][i] >= cH);
                nHB += (u[r][i] >= cHB);
                nL  += (u[r][i] >= cL);
            }
            pk[r] = nH | (nHB << 10) | (nL << 20);
        }
        pk[0] = __reduce_add_sync(0xffffffffu, pk[0]);
        pk[1] = __reduce_add_sync(0xffffffffu, pk[1]);
        #pragma unroll
        for (int r = 0; r < 2; r++) {
            int nH  = pk[r] & 1023;
            int nHB = (pk[r] >> 10) & 1023;
            int nL  = (pk[r] >> 20) & 1023;
            if (nHB >= cnt[r])      { pre[r] |= m1 | m0; cur[r] = nHB; }
            else if (nH >= cnt[r])  { pre[r] |= m1;      cur[r] = nH; }
            else if (nL >= cnt[r])  { pre[r] |= m0;      cur[r] = nL; }
            done |= (cur[r] == cnt[r]) << r;
        }
        if (done == 3) break;
    }

    int h0 = 0, h1 = 0;
    #pragma unroll
    for (int i = 0; i < 17; i++) {
        h0 += (((pm[0] >> i) & 1u) && (u[0][i] >= pre[0])) ? 1 : 0;
        h1 += (((pm[1] >> i) & 1u) && (u[1][i] >= pre[1])) ? 1 : 0;
    }
    int hh = h0 | (h1 << 16);
    hh = __reduce_add_sync(0xffffffffu, hh);

    if (lane == 0) {
        float sc = (float)(hh & 0xffff) / (float)cnt[0]
                 + (float)(hh >> 16)    / (float)cnt[1];
        atomicAdd(&out[0], lsum * (1.0f / ((float)NB * (float)NC)));
        atomicAdd(&out[1], sc * (1.0f / (float)NB));
    }
}

// ---------------------------------------------------------------------------
// launch: conv(+zero) full-grid -> gemm in 2 chunks; reduce chunk c overlaps
// gemm chunk c+1 on a second stream. No conv chunking (R7's mistake).
// ---------------------------------------------------------------------------
extern "C" void kernel_launch(void* const* d_in, const int* in_sizes, int n_in,
                              void* d_out, int out_size) {
    const float *x = nullptr, *y = nullptr, *W = nullptr, *b = nullptr, *pwt = nullptr;
    int n527 = 0;
    for (int i = 0; i < n_in; i++) {
        if      (in_sizes[i] == NB * ND) x = (const float*)d_in[i];
        else if (in_sizes[i] == NB * NC) y = (const float*)d_in[i];
        else if (in_sizes[i] == NC * ND) W = (const float*)d_in[i];
        else if (in_sizes[i] == NC) {
            if (n527 == 0) b = (const float*)d_in[i];
            else           pwt = (const float*)d_in[i];
            n527++;
        }
    }
    float* out = (float*)d_out;

    static cudaStream_t sRed = nullptr;
    static cudaEvent_t evG[NCH], evJoin;
    static int inited = 0;
    if (!inited) {
        cudaFuncSetAttribute(k_gemm, cudaFuncAttributeMaxDynamicSharedMemorySize, SMEM_DYN);
        cudaStreamCreateWithFlags(&sRed, cudaStreamNonBlocking);
        cudaEventCreateWithFlags(&evJoin, cudaEventDisableTiming);
        for (int c = 0; c < NCH; c++)
            cudaEventCreateWithFlags(&evG[c], cudaEventDisableTiming);
        inited = 1;
    }

    __half *xh, *wh;
    cudaGetSymbolAddress((void**)&xh, g_Xh);
    cudaGetSymbolAddress((void**)&wh, g_Wh);

    k_conv<<<2048, 256>>>(x, W, out);   // also zeroes out[0..1]

    dim3 gg(NPAD / BN, CRB);            // (3, 128) per chunk
    for (int c = 0; c < NCH; c++) {
        k_gemm<<<gg, 256, SMEM_DYN>>>(xh, wh, b, c * CROWS);
        cudaEventRecord(evG[c], 0);
        cudaStreamWaitEvent(sRed, evG[c], 0);
        k_reduce<<<CROWS / 16, 256, 0, sRed>>>(y, pwt, out, c * CROWS);
    }

    cudaEventRecord(evJoin, sRed);
    cudaStreamWaitEvent(0, evJoin, 0);
}

// round 10
// speedup vs baseline: 1.1382x; 1.0003x over previous
#include <cuda_runtime.h>
#include <cuda_fp16.h>
#include <cstdint>

#define NB 32768
#define ND 512
#define NC 527
#define NPAD 576     // 3 * 192

#define BM 128
#define BN 192
#define BKH 32          // halfs per K-stage
#define RPAD 40         // padded row stride in halfs (80B; conflict-free LDSM)
#define STAGES 4
#define NIT (ND / BKH)  // 16

#define NCH 2
#define CRB  (NB / BM / NCH)    // 128 row-blocks per chunk
#define CROWS (NB / NCH)        // 16384 rows per chunk

#define A_STAGE_H (BM * RPAD)   // 5120 halfs
#define B_STAGE_H (BN * RPAD)   // 7680 halfs
#define STAGE_H   (A_STAGE_H + B_STAGE_H)
#define SMEM_DYN  (STAGES * STAGE_H * 2)   // 102,400 B

// Scratch: fp16 copies of X and (padded) W, fp32 logits.
__device__ __half g_Xh[(size_t)NB * ND];     // 32 MB
__device__ __half g_Wh[(size_t)NPAD * ND];   // 0.56 MB (rows >= NC zeroed)
__device__ float  g_LOG[(size_t)NB * NPAD];  // 75.5 MB

// ---------------------------------------------------------------------------
// K0: fp32 -> fp16 conversion (full tensors, full grid) + output zeroing
// ---------------------------------------------------------------------------
__global__ __launch_bounds__(256)
void k_conv(const float* __restrict__ X, const float* __restrict__ W,
            float* __restrict__ out) {
    if (blockIdx.x == 0 && threadIdx.x < 2) out[threadIdx.x] = 0.0f;

    const size_t stride = (size_t)gridDim.x * blockDim.x;
    size_t i0 = (size_t)blockIdx.x * blockDim.x + threadIdx.x;

    const float4* X4 = (const float4*)X;
    const size_t nx4 = (size_t)NB * ND / 4;
    for (size_t j = i0; j < nx4; j += stride) {
        float4 v = X4[j];
        __half2 h0 = __floats2half2_rn(v.x, v.y);
        __half2 h1 = __floats2half2_rn(v.z, v.w);
        uint2 p;
        p.x = *(uint32_t*)&h0; p.y = *(uint32_t*)&h1;
        *(uint2*)&g_Xh[j * 4] = p;
    }

    const size_t nw4 = (size_t)NPAD * ND / 4;
    for (size_t j = i0; j < nw4; j += stride) {
        size_t row = j >> 7;            // 128 float4 per 512-col row
        uint2 p = make_uint2(0u, 0u);
        if (row < NC) {
            float4 v = *(const float4*)&W[j * 4];
            __half2 h0 = __floats2half2_rn(v.x, v.y);
            __half2 h1 = __floats2half2_rn(v.z, v.w);
            p.x = *(uint32_t*)&h0; p.y = *(uint32_t*)&h1;
        }
        *(uint2*)&g_Wh[j * 4] = p;
    }
}

__device__ __forceinline__ void mma_f16(float* c, const uint32_t* a, const uint32_t* b) {
    asm volatile(
        "mma.sync.aligned.m16n8k16.row.col.f32.f16.f16.f32 "
        "{%0,%1,%2,%3}, {%4,%5,%6,%7}, {%8,%9}, {%0,%1,%2,%3};\n"
        : "+f"(c[0]), "+f"(c[1]), "+f"(c[2]), "+f"(c[3])
        : "r"(a[0]), "r"(a[1]), "r"(a[2]), "r"(a[3]), "r"(b[0]), "r"(b[1]));
}

__device__ __forceinline__ void ldsm_x4(uint32_t* r, uint32_t addr) {
    asm volatile("ldmatrix.sync.aligned.m8n8.x4.shared.b16 {%0,%1,%2,%3}, [%4];"
                 : "=r"(r[0]), "=r"(r[1]), "=r"(r[2]), "=r"(r[3]) : "r"(addr));
}

// ---------------------------------------------------------------------------
// K1: fp16 mma GEMM for one row chunk.
// CTA 128x192 with 512 threads / 16 warps (4m x 4n), warp tile 32x48.
// Same smem + traffic as the 8-warp version, 2x the warps to hide latency.
// ---------------------------------------------------------------------------
__global__ __launch_bounds__(512, 1)
void k_gemm(const __half* __restrict__ Xh, const __half* __restrict__ Wh,
            const float* __restrict__ bias, int rowOff) {
    extern __shared__ __half smh[];   // [STAGES][A | B], RPAD-padded rows
    __shared__ float sBias[BN];

    const int tid  = threadIdx.x;
    const int lane = tid & 31;
    const int warp = tid >> 5;      // 0..15
    const int wm   = warp & 3;      // 0..3
    const int wn   = warp >> 2;     // 0..3
    const int g    = lane >> 2;     // 0..7
    const int t    = lane & 3;      // 0..3

    const int col0 = blockIdx.x * BN;
    const int row0 = rowOff + blockIdx.y * BM;

    for (int i = tid; i < BN; i += 512)
        sBias[i] = (col0 + i < NC) ? bias[col0 + i] : 0.0f;

    const int aRow = (lane & 7) + ((lane >> 3) & 1) * 8;
    const int aCol = (lane >> 4) * 8;
    const int bRow = (lane & 7) + (lane >> 4) * 8;
    const int bCol = ((lane >> 3) & 1) * 8;

    const uint32_t smBase = (uint32_t)__cvta_generic_to_shared(smh);

    float acc[2][6][4];
    #pragma unroll
    for (int i = 0; i < 2; i++)
        #pragma unroll
        for (int j = 0; j < 6; j++)
            #pragma unroll
            for (int r = 0; r < 4; r++) acc[i][j][r] = 0.0f;

    auto load_stage = [&](int kt, int buf) {
        __half* sA = smh + buf * STAGE_H;
        __half* sB = sA + A_STAGE_H;
        const __half* Xb = Xh + (size_t)row0 * ND + kt * BKH;
        {                                           // A: 512 x 16B chunks / 512 thr
            int r = tid >> 2, c = (tid & 3) * 8;
            uint32_t dst = (uint32_t)__cvta_generic_to_shared(&sA[r * RPAD + c]);
            asm volatile("cp.async.ca.shared.global [%0], [%1], 16;\n"
                         :: "r"(dst), "l"(Xb + (size_t)r * ND + c));
        }
        const __half* Wb = Wh + (size_t)col0 * ND + kt * BKH;
        #pragma unroll
        for (int i = 0; i < 2; i++) {               // B: 768 x 16B chunks
            int id = i * 512 + tid;
            if (id < 768) {
                int r = id >> 2, c = (id & 3) * 8;
                uint32_t dst = (uint32_t)__cvta_generic_to_shared(&sB[r * RPAD + c]);
                asm volatile("cp.async.ca.shared.global [%0], [%1], 16;\n"
                             :: "r"(dst), "l"(Wb + (size_t)r * ND + c));
            }
        }
    };

    auto compute_stage = [&](int buf) {
        const uint32_t sA = smBase + (buf * STAGE_H) * 2;
        const uint32_t sB = sA + A_STAGE_H * 2;
        #pragma unroll
        for (int ks = 0; ks < 2; ks++) {           // 2 x k16 per BK=32
            const int k0 = ks * 16;
            uint32_t a[2][4], bf[3][4];
            #pragma unroll
            for (int mt = 0; mt < 2; mt++) {
                int r = wm * 32 + mt * 16 + aRow;
                ldsm_x4(a[mt], sA + (r * RPAD + k0 + aCol) * 2);
            }
            #pragma unroll
            for (int nb = 0; nb < 3; nb++) {       // 2 n-tiles per LDSM
                int c = wn * 48 + nb * 16 + bRow;
                ldsm_x4(bf[nb], sB + (c * RPAD + k0 + bCol) * 2);
            }
            #pragma unroll
            for (int mt = 0; mt < 2; mt++)
                #pragma unroll
                for (int nt = 0; nt < 6; nt++)
                    mma_f16(acc[mt][nt], a[mt], &bf[nt >> 1][(nt & 1) * 2]);
        }
    };

    load_stage(0, 0); asm volatile("cp.async.commit_group;\n");
    load_stage(1, 1); asm volatile("cp.async.commit_group;\n");
    load_stage(2, 2); asm volatile("cp.async.commit_group;\n");

    for (int it = 0; it < NIT; it++) {
        asm volatile("cp.async.wait_group 2;\n");
        __syncthreads();
        if (it + 3 < NIT) load_stage(it + 3, (it + 3) & 3);   // prefetch first
        asm volatile("cp.async.commit_group;\n");
        compute_stage(it & 3);
    }

    // epilogue: bias add + store fp32 logits
    #pragma unroll
    for (int mt = 0; mt < 2; mt++) {
        int gr = row0 + wm * 32 + mt * 16 + g;
        #pragma unroll
        for (int nt = 0; nt < 6; nt++) {
            int ci = wn * 48 + nt * 8 + 2 * t;
            float bv0 = sBias[ci], bv1 = sBias[ci + 1];
            int gc = col0 + ci;
            float2 v0 = make_float2(acc[mt][nt][0] + bv0, acc[mt][nt][1] + bv1);
            float2 v1 = make_float2(acc[mt][nt][2] + bv0, acc[mt][nt][3] + bv1);
            *(float2*)&g_LOG[(size_t)(gr    ) * NPAD + gc] = v0;
            *(float2*)&g_LOG[(size_t)(gr + 8) * NPAD + gc] = v1;
        }
    }
}

// ---------------------------------------------------------------------------
// K2: per-row BCE loss + exact top-k hit rate, one row chunk.
// One warp handles two rows; 2-bit-per-pass radix select. (R6 core.)
// ---------------------------------------------------------------------------
__global__ __launch_bounds__(256)
void k_reduce(const float* __restrict__ Y, const float* __restrict__ pw,
              float* __restrict__ out, int rowOff) {
    const int warp = threadIdx.x >> 5;
    const int lane = threadIdx.x & 31;
    const int row0 = rowOff + (blockIdx.x * 8 + warp) * 2;

    unsigned u[2][17];
    unsigned pm[2];
    int      cnt[2];
    float lsum = 0.0f;

    #pragma unroll
    for (int r = 0; r < 2; r++) {
        const float* lg = g_LOG + (size_t)(row0 + r) * NPAD;
        const float* yr = Y + (size_t)(row0 + r) * NC;
        unsigned m = 0;
        #pragma unroll
        for (int i = 0; i < 17; i++) {
            int c = lane + 32 * i;        // max 543 < NPAD: logits in-bounds
            bool v = (c < NC);
            float z  = lg[c];
            float yy = v ? yr[c] : 0.0f;
            float p  = v ? pw[c] : 0.0f;
            float e  = __expf(-fabsf(z));
            float sp = fmaxf(z, 0.0f) + __logf(1.0f + e);   // softplus(z)
            float w  = 1.0f + yy * (p - 1.0f);
            lsum += v ? (w * sp - p * yy * z) : 0.0f;
            m |= (yy != 0.0f) ? (1u << i) : 0u;
            unsigned bb = __float_as_uint(z);
            unsigned uu = bb ^ (((unsigned)((int)bb >> 31)) | 0x80000000u);
            u[r][i] = v ? uu : 0u;        // 0 sorts below every valid key
        }
        pm[r]  = m;
        cnt[r] = __popc(m);
    }

    {
        int q = cnt[0] | (cnt[1] << 16);
        q = __reduce_add_sync(0xffffffffu, q);
        cnt[0] = q & 0xffff; cnt[1] = q >> 16;
    }
    #pragma unroll
    for (int o = 16; o; o >>= 1) lsum += __shfl_xor_sync(0xffffffffu, lsum, o);

    unsigned pre[2] = {0u, 0u};
    int cur[2] = {0x7fffffff, 0x7fffffff};
    int done = 0;
    #pragma unroll 1
    for (int bit = 30; bit >= 0; bit -= 2) {
        const unsigned m1 = 2u << bit;
        const unsigned m0 = 1u << bit;
        int pk[2];
        #pragma unroll
        for (int r = 0; r < 2; r++) {
            const unsigned cH  = pre[r] | m1;
            const unsigned cHB = cH | m0;
            const unsigned cL  = pre[r] | m0;
            int nH = 0, nHB = 0, nL = 0;
            #pragma unroll
            for (int i = 0; i < 17; i++) {
                nH  += (u[r][i] >= cH);
                nHB += (u[r][i] >= cHB);
                nL  += (u[r][i] >= cL);
            }
            pk[r] = nH | (nHB << 10) | (nL << 20);
        }
        pk[0] = __reduce_add_sync(0xffffffffu, pk[0]);
        pk[1] = __reduce_add_sync(0xffffffffu, pk[1]);
        #pragma unroll
        for (int r = 0; r < 2; r++) {
            int nH  = pk[r] & 1023;
            int nHB = (pk[r] >> 10) & 1023;
            int nL  = (pk[r] >> 20) & 1023;
            if (nHB >= cnt[r])      { pre[r] |= m1 | m0; cur[r] = nHB; }
            else if (nH >= cnt[r])  { pre[r] |= m1;      cur[r] = nH; }
            else if (nL >= cnt[r])  { pre[r] |= m0;      cur[r] = nL; }
            done |= (cur[r] == cnt[r]) << r;
        }
        if (done == 3) break;
    }

    int h0 = 0, h1 = 0;
    #pragma unroll
    for (int i = 0; i < 17; i++) {
        h0 += (((pm[0] >> i) & 1u) && (u[0][i] >= pre[0])) ? 1 : 0;
        h1 += (((pm[1] >> i) & 1u) && (u[1][i] >= pre[1])) ? 1 : 0;
    }
    int hh = h0 | (h1 << 16);
    hh = __reduce_add_sync(0xffffffffu, hh);

    if (lane == 0) {
        float sc = (float)(hh & 0xffff) / (float)cnt[0]
                 + (float)(hh >> 16)    / (float)cnt[1];
        atomicAdd(&out[0], lsum * (1.0f / ((float)NB * (float)NC)));
        atomicAdd(&out[1], sc * (1.0f / (float)NB));
    }
}

// ---------------------------------------------------------------------------
// launch: conv(+zero) full-grid -> gemm in 2 chunks; reduce chunk c overlaps
// gemm chunk c+1 on a second stream.
// ---------------------------------------------------------------------------
extern "C" void kernel_launch(void* const* d_in, const int* in_sizes, int n_in,
                              void* d_out, int out_size) {
    const float *x = nullptr, *y = nullptr, *W = nullptr, *b = nullptr, *pwt = nullptr;
    int n527 = 0;
    for (int i = 0; i < n_in; i++) {
        if      (in_sizes[i] == NB * ND) x = (const float*)d_in[i];
        else if (in_sizes[i] == NB * NC) y = (const float*)d_in[i];
        else if (in_sizes[i] == NC * ND) W = (const float*)d_in[i];
        else if (in_sizes[i] == NC) {
            if (n527 == 0) b = (const float*)d_in[i];
            else           pwt = (const float*)d_in[i];
            n527++;
        }
    }
    float* out = (float*)d_out;

    static cudaStream_t sRed = nullptr;
    static cudaEvent_t evG[NCH], evJoin;
    static int inited = 0;
    if (!inited) {
        cudaFuncSetAttribute(k_gemm, cudaFuncAttributeMaxDynamicSharedMemorySize, SMEM_DYN);
        cudaStreamCreateWithFlags(&sRed, cudaStreamNonBlocking);
        cudaEventCreateWithFlags(&evJoin, cudaEventDisableTiming);
        for (int c = 0; c < NCH; c++)
            cudaEventCreateWithFlags(&evG[c], cudaEventDisableTiming);
        inited = 1;
    }

    __half *xh, *wh;
    cudaGetSymbolAddress((void**)&xh, g_Xh);
    cudaGetSymbolAddress((void**)&wh, g_Wh);

    k_conv<<<2048, 256>>>(x, W, out);   // also zeroes out[0..1]

    dim3 gg(NPAD / BN, CRB);            // (3, 128) per chunk
    for (int c = 0; c < NCH; c++) {
        k_gemm<<<gg, 512, SMEM_DYN>>>(xh, wh, b, c * CROWS);
        cudaEventRecord(evG[c], 0);
        cudaStreamWaitEvent(sRed, evG[c], 0);
        k_reduce<<<CROWS / 16, 256, 0, sRed>>>(y, pwt, out, c * CROWS);
    }

    cudaEventRecord(evJoin, sRed);
    cudaStreamWaitEvent(0, evJoin, 0);
}

// round 11
// speedup vs baseline: 1.2517x; 1.0998x over previous
#include <cuda_runtime.h>
#include <cuda_fp16.h>
#include <cuda.h>
#include <cstdint>

#define NB 32768
#define ND 512
#define NC 527
#define NPAD 576     // 3 * 192

#define BM 128
#define BN 192
#define BKH 64          // halfs per K-stage (128 B = one SW128 row)
#define NITK (ND / BKH) // 8
#define NCH 2
#define CRB  (NB / BM / NCH)    // 128 row-blocks per chunk
#define CROWS (NB / NCH)        // 16384 rows per chunk

#define A_BYTES (BM * 128)      // 16384
#define B_BYTES (BN * 128)      // 24576
#define STG_BYTES (A_BYTES + B_BYTES)   // 40960
#define SMEM_DYN (4 * STG_BYTES + 1024) // 164,864

// Scratch: fp16 copies of X and (padded) W, fp32 logits, tensormaps.
__device__ __half g_Xh[(size_t)NB * ND];     // 32 MB
__device__ __half g_Wh[(size_t)NPAD * ND];   // 0.56 MB (rows >= NC zeroed)
__device__ float  g_LOG[(size_t)NB * NPAD];  // 75.5 MB
__device__ __align__(128) CUtensorMap g_tmaX;
__device__ __align__(128) CUtensorMap g_tmaW;

// ---------------------------------------------------------------------------
// K0: fp32 -> fp16 conversion (full tensors, full grid) + output zeroing
// ---------------------------------------------------------------------------
__global__ __launch_bounds__(256)
void k_conv(const float* __restrict__ X, const float* __restrict__ W,
            float* __restrict__ out) {
    if (blockIdx.x == 0 && threadIdx.x < 2) out[threadIdx.x] = 0.0f;

    const size_t stride = (size_t)gridDim.x * blockDim.x;
    size_t i0 = (size_t)blockIdx.x * blockDim.x + threadIdx.x;

    const float4* X4 = (const float4*)X;
    const size_t nx4 = (size_t)NB * ND / 4;
    for (size_t j = i0; j < nx4; j += stride) {
        float4 v = X4[j];
        __half2 h0 = __floats2half2_rn(v.x, v.y);
        __half2 h1 = __floats2half2_rn(v.z, v.w);
        uint2 p;
        p.x = *(uint32_t*)&h0; p.y = *(uint32_t*)&h1;
        *(uint2*)&g_Xh[j * 4] = p;
    }

    const size_t nw4 = (size_t)NPAD * ND / 4;
    for (size_t j = i0; j < nw4; j += stride) {
        size_t row = j >> 7;            // 128 float4 per 512-col row
        uint2 p = make_uint2(0u, 0u);
        if (row < NC) {
            float4 v = *(const float4*)&W[j * 4];
            __half2 h0 = __floats2half2_rn(v.x, v.y);
            __half2 h1 = __floats2half2_rn(v.z, v.w);
            p.x = *(uint32_t*)&h0; p.y = *(uint32_t*)&h1;
        }
        *(uint2*)&g_Wh[j * 4] = p;
    }
}

__device__ __forceinline__ void mma_f16(float* c, const uint32_t* a, const uint32_t* b) {
    asm volatile(
        "mma.sync.aligned.m16n8k16.row.col.f32.f16.f16.f32 "
        "{%0,%1,%2,%3}, {%4,%5,%6,%7}, {%8,%9}, {%0,%1,%2,%3};\n"
        : "+f"(c[0]), "+f"(c[1]), "+f"(c[2]), "+f"(c[3])
        : "r"(a[0]), "r"(a[1]), "r"(a[2]), "r"(a[3]), "r"(b[0]), "r"(b[1]));
}

__device__ __forceinline__ void ldsm_x4(uint32_t* r, uint32_t addr) {
    asm volatile("ldmatrix.sync.aligned.m8n8.x4.shared.b16 {%0,%1,%2,%3}, [%4];"
                 : "=r"(r[0]), "=r"(r[1]), "=r"(r[2]), "=r"(r[3]) : "r"(addr));
}

__device__ __forceinline__ void tma2d(uint32_t dst, const CUtensorMap* m,
                                      int cx, int cy, uint32_t mb) {
    asm volatile(
        "cp.async.bulk.tensor.2d.shared::cta.global.tile.mbarrier::complete_tx::bytes "
        "[%0], [%1, {%2, %3}], [%4];"
        :: "r"(dst), "l"(m), "r"(cx), "r"(cy), "r"(mb) : "memory");
}

__device__ __forceinline__ void mbar_wait(uint32_t addr, uint32_t parity) {
    asm volatile(
        "{\n\t.reg .pred P;\n\t"
        "W_%=:\n\t"
        "mbarrier.try_wait.parity.acquire.cta.shared::cta.b64 P, [%0], %1, 0x989680;\n\t"
        "@!P bra W_%=;\n\t}"
        :: "r"(addr), "r"(parity) : "memory");
}

#define SWZ(o) ((o) ^ (((o) >> 3) & 0x70))

// ---------------------------------------------------------------------------
// K1: fp16 mma GEMM, TMA-staged. CTA 128x192, 512 thr / 16 warps (4m x 4n),
// warp tile 32x48, K staged 64 halfs (SW128) x 8, 4-deep mbarrier ring.
// ---------------------------------------------------------------------------
__global__ __launch_bounds__(512, 1)
void k_gemm(const float* __restrict__ bias, int rowOff) {
    extern __shared__ char dsm[];
    __shared__ float sBias[BN];
    __shared__ __align__(8) uint64_t mbar[4];

    const int tid  = threadIdx.x;
    const int lane = tid & 31;
    const int warp = tid >> 5;      // 0..15
    const int wm   = warp & 3;      // 0..3
    const int wn   = warp >> 2;     // 0..3
    const int g    = lane >> 2;     // 0..7
    const int t    = lane & 3;      // 0..3

    const int col0 = blockIdx.x * BN;
    const int row0 = rowOff + blockIdx.y * BM;

    uint32_t raw  = (uint32_t)__cvta_generic_to_shared(dsm);
    uint32_t base = (raw + 1023) & ~1023u;
    const uint32_t mb0 = (uint32_t)__cvta_generic_to_shared(&mbar[0]);

    for (int i = tid; i < BN; i += 512)
        sBias[i] = (col0 + i < NC) ? bias[col0 + i] : 0.0f;

    if (tid == 0) {
        #pragma unroll
        for (int s = 0; s < 4; s++)
            asm volatile("mbarrier.init.shared.b64 [%0], 1;" :: "r"(mb0 + 8 * s) : "memory");
        asm volatile("fence.proxy.async.shared::cta;" ::: "memory");
    }
    __syncthreads();

    auto issue = [&](int s) {       // tid 0 only
        const uint32_t dst = base + (s & 3) * STG_BYTES;
        const uint32_t mbs = mb0 + (s & 3) * 8;
        asm volatile("mbarrier.arrive.expect_tx.shared.b64 _, [%0], %1;"
                     :: "r"(mbs), "r"((uint32_t)STG_BYTES) : "memory");
        tma2d(dst,           &g_tmaX, s * BKH, row0, mbs);
        tma2d(dst + A_BYTES, &g_tmaW, s * BKH, col0, mbs);
    };

    if (tid == 0) { issue(0); issue(1); issue(2); }

    // LDSM per-lane row/column-byte offsets
    const int aRow  = (lane & 7) + ((lane >> 3) & 1) * 8;
    const int aColB = (lane >> 4) * 16;
    const int bRow  = (lane & 7) + (lane >> 4) * 8;
    const int bColB = ((lane >> 3) & 1) * 16;

    float acc[2][6][4];
    #pragma unroll
    for (int i = 0; i < 2; i++)
        #pragma unroll
        for (int j = 0; j < 6; j++)
            #pragma unroll
            for (int r = 0; r < 4; r++) acc[i][j][r] = 0.0f;

    for (int it = 0; it < NITK; it++) {
        mbar_wait(mb0 + (it & 3) * 8, (it >> 2) & 1);
        __syncthreads();                 // all warps done with buf (it-1)&3
        if (tid == 0 && it + 3 < NITK) issue(it + 3);

        const uint32_t sA = base + (it & 3) * STG_BYTES;
        const uint32_t sB = sA + A_BYTES;
        #pragma unroll
        for (int ks = 0; ks < 4; ks++) {           // 4 x k16 per 64-half stage
            const int kb = ks * 32;                // byte offset in 128B row
            uint32_t a[2][4], bf[3][4];
            #pragma unroll
            for (int mt = 0; mt < 2; mt++) {
                int r = wm * 32 + mt * 16 + aRow;
                uint32_t off = (uint32_t)(r * 128 + kb + aColB);
                ldsm_x4(a[mt], sA + SWZ(off));
            }
            #pragma unroll
            for (int nb = 0; nb < 3; nb++) {       // 2 n-tiles per LDSM
                int c = wn * 48 + nb * 16 + bRow;
                uint32_t off = (uint32_t)(c * 128 + kb + bColB);
                ldsm_x4(bf[nb], sB + SWZ(off));
            }
            #pragma unroll
            for (int mt = 0; mt < 2; mt++)
                #pragma unroll
                for (int nt = 0; nt < 6; nt++)
                    mma_f16(acc[mt][nt], a[mt], &bf[nt >> 1][(nt & 1) * 2]);
        }
    }

    // epilogue: bias add + store fp32 logits
    #pragma unroll
    for (int mt = 0; mt < 2; mt++) {
        int gr = row0 + wm * 32 + mt * 16 + g;
        #pragma unroll
        for (int nt = 0; nt < 6; nt++) {
            int ci = wn * 48 + nt * 8 + 2 * t;
            float bv0 = sBias[ci], bv1 = sBias[ci + 1];
            int gc = col0 + ci;
            float2 v0 = make_float2(acc[mt][nt][0] + bv0, acc[mt][nt][1] + bv1);
            float2 v1 = make_float2(acc[mt][nt][2] + bv0, acc[mt][nt][3] + bv1);
            *(float2*)&g_LOG[(size_t)(gr    ) * NPAD + gc] = v0;
            *(float2*)&g_LOG[(size_t)(gr + 8) * NPAD + gc] = v1;
        }
    }
}

// ---------------------------------------------------------------------------
// K2: per-row BCE loss + exact top-k hit rate, one row chunk.
// One warp handles two rows; 2-bit-per-pass radix select. (R6 core.)
// ---------------------------------------------------------------------------
__global__ __launch_bounds__(256)
void k_reduce(const float* __restrict__ Y, const float* __restrict__ pw,
              float* __restrict__ out, int rowOff) {
    const int warp = threadIdx.x >> 5;
    const int lane = threadIdx.x & 31;
    const int row0 = rowOff + (blockIdx.x * 8 + warp) * 2;

    unsigned u[2][17];
    unsigned pm[2];
    int      cnt[2];
    float lsum = 0.0f;

    #pragma unroll
    for (int r = 0; r < 2; r++) {
        const float* lg = g_LOG + (size_t)(row0 + r) * NPAD;
        const float* yr = Y + (size_t)(row0 + r) * NC;
        unsigned m = 0;
        #pragma unroll
        for (int i = 0; i < 17; i++) {
            int c = lane + 32 * i;        // max 543 < NPAD: logits in-bounds
            bool v = (c < NC);
            float z  = lg[c];
            float yy = v ? yr[c] : 0.0f;
            float p  = v ? pw[c] : 0.0f;
            float e  = __expf(-fabsf(z));
            float sp = fmaxf(z, 0.0f) + __logf(1.0f + e);   // softplus(z)
            float w  = 1.0f + yy * (p - 1.0f);
            lsum += v ? (w * sp - p * yy * z) : 0.0f;
            m |= (yy != 0.0f) ? (1u << i) : 0u;
            unsigned bb = __float_as_uint(z);
            unsigned uu = bb ^ (((unsigned)((int)bb >> 31)) | 0x80000000u);
            u[r][i] = v ? uu : 0u;        // 0 sorts below every valid key
        }
        pm[r]  = m;
        cnt[r] = __popc(m);
    }

    {
        int q = cnt[0] | (cnt[1] << 16);
        q = __reduce_add_sync(0xffffffffu, q);
        cnt[0] = q & 0xffff; cnt[1] = q >> 16;
    }
    #pragma unroll
    for (int o = 16; o; o >>= 1) lsum += __shfl_xor_sync(0xffffffffu, lsum, o);

    unsigned pre[2] = {0u, 0u};
    int cur[2] = {0x7fffffff, 0x7fffffff};
    int done = 0;
    #pragma unroll 1
    for (int bit = 30; bit >= 0; bit -= 2) {
        const unsigned m1 = 2u << bit;
        const unsigned m0 = 1u << bit;
        int pk[2];
        #pragma unroll
        for (int r = 0; r < 2; r++) {
            const unsigned cH  = pre[r] | m1;
            const unsigned cHB = cH | m0;
            const unsigned cL  = pre[r] | m0;
            int nH = 0, nHB = 0, nL = 0;
            #pragma unroll
            for (int i = 0; i < 17; i++) {
                nH  += (u[r][i] >= cH);
                nHB += (u[r][i] >= cHB);
                nL  += (u[r][i] >= cL);
            }
            pk[r] = nH | (nHB << 10) | (nL << 20);
        }
        pk[0] = __reduce_add_sync(0xffffffffu, pk[0]);
        pk[1] = __reduce_add_sync(0xffffffffu, pk[1]);
        #pragma unroll
        for (int r = 0; r < 2; r++) {
            int nH  = pk[r] & 1023;
            int nHB = (pk[r] >> 10) & 1023;
            int nL  = (pk[r] >> 20) & 1023;
            if (nHB >= cnt[r])      { pre[r] |= m1 | m0; cur[r] = nHB; }
            else if (nH >= cnt[r])  { pre[r] |= m1;      cur[r] = nH; }
            else if (nL >= cnt[r])  { pre[r] |= m0;      cur[r] = nL; }
            done |= (cur[r] == cnt[r]) << r;
        }
        if (done == 3) break;
    }

    int h0 = 0, h1 = 0;
    #pragma unroll
    for (int i = 0; i < 17; i++) {
        h0 += (((pm[0] >> i) & 1u) && (u[0][i] >= pre[0])) ? 1 : 0;
        h1 += (((pm[1] >> i) & 1u) && (u[1][i] >= pre[1])) ? 1 : 0;
    }
    int hh = h0 | (h1 << 16);
    hh = __reduce_add_sync(0xffffffffu, hh);

    if (lane == 0) {
        float sc = (float)(hh & 0xffff) / (float)cnt[0]
                 + (float)(hh >> 16)    / (float)cnt[1];
        atomicAdd(&out[0], lsum * (1.0f / ((float)NB * (float)NC)));
        atomicAdd(&out[1], sc * (1.0f / (float)NB));
    }
}

// ---------------------------------------------------------------------------
// launch: conv(+zero) -> gemm in 2 chunks; reduce chunk c overlaps gemm c+1.
// Tensormaps built once on the first (uncaptured) call.
// ---------------------------------------------------------------------------
typedef CUresult (*EncodeFn)(CUtensorMap*, CUtensorMapDataType, cuuint32_t, void*,
                             const cuuint64_t*, const cuuint64_t*, const cuuint32_t*,
                             const cuuint32_t*, CUtensorMapInterleave, CUtensorMapSwizzle,
                             CUtensorMapL2promotion, CUtensorMapFloatOOBfill);

extern "C" void kernel_launch(void* const* d_in, const int* in_sizes, int n_in,
                              void* d_out, int out_size) {
    const float *x = nullptr, *y = nullptr, *W = nullptr, *b = nullptr, *pwt = nullptr;
    int n527 = 0;
    for (int i = 0; i < n_in; i++) {
        if      (in_sizes[i] == NB * ND) x = (const float*)d_in[i];
        else if (in_sizes[i] == NB * NC) y = (const float*)d_in[i];
        else if (in_sizes[i] == NC * ND) W = (const float*)d_in[i];
        else if (in_sizes[i] == NC) {
            if (n527 == 0) b = (const float*)d_in[i];
            else           pwt = (const float*)d_in[i];
            n527++;
        }
    }
    float* out = (float*)d_out;

    static cudaStream_t sRed = nullptr;
    static cudaEvent_t evG[NCH], evJoin;
    static int inited = 0;
    if (!inited) {
        cudaFuncSetAttribute(k_gemm, cudaFuncAttributeMaxDynamicSharedMemorySize, SMEM_DYN);
        cudaStreamCreateWithFlags(&sRed, cudaStreamNonBlocking);
        cudaEventCreateWithFlags(&evJoin, cudaEventDisableTiming);
        for (int c = 0; c < NCH; c++)
            cudaEventCreateWithFlags(&evG[c], cudaEventDisableTiming);

        // Build TMA descriptors for g_Xh / g_Wh (first call only, not captured)
        void* xh_ = nullptr; void* wh_ = nullptr;
        cudaGetSymbolAddress(&xh_, g_Xh);
        cudaGetSymbolAddress(&wh_, g_Wh);
        EncodeFn enc = nullptr;
        cudaDriverEntryPointQueryResult qres;
        cudaGetDriverEntryPoint("cuTensorMapEncodeTiled", (void**)&enc,
                                cudaEnableDefault, &qres);
        CUtensorMap hx{}, hw{};
        {
            cuuint64_t dims[2]    = {ND, NB};
            cuuint64_t strides[1] = {ND * 2};
            cuuint32_t box[2]     = {BKH, BM};
            cuuint32_t es[2]      = {1, 1};
            enc(&hx, CU_TENSOR_MAP_DATA_TYPE_FLOAT16, 2, xh_, dims, strides, box, es,
                CU_TENSOR_MAP_INTERLEAVE_NONE, CU_TENSOR_MAP_SWIZZLE_128B,
                CU_TENSOR_MAP_L2_PROMOTION_L2_128B, CU_TENSOR_MAP_FLOAT_OOB_FILL_NONE);
        }
        {
            cuuint64_t dims[2]    = {ND, NPAD};
            cuuint64_t strides[1] = {ND * 2};
            cuuint32_t box[2]     = {BKH, BN};
            cuuint32_t es[2]      = {1, 1};
            enc(&hw, CU_TENSOR_MAP_DATA_TYPE_FLOAT16, 2, wh_, dims, strides, box, es,
                CU_TENSOR_MAP_INTERLEAVE_NONE, CU_TENSOR_MAP_SWIZZLE_128B,
                CU_TENSOR_MAP_L2_PROMOTION_L2_128B, CU_TENSOR_MAP_FLOAT_OOB_FILL_NONE);
        }
        cudaMemcpyToSymbol(g_tmaX, &hx, sizeof(CUtensorMap));
        cudaMemcpyToSymbol(g_tmaW, &hw, sizeof(CUtensorMap));
        inited = 1;
    }

    k_conv<<<2048, 256>>>(x, W, out);   // also zeroes out[0..1]

    dim3 gg(NPAD / BN, CRB);            // (3, 128) per chunk
    for (int c = 0; c < NCH; c++) {
        k_gemm<<<gg, 512, SMEM_DYN>>>(b, c * CROWS);
        cudaEventRecord(evG[c], 0);
        cudaStreamWaitEvent(sRed, evG[c], 0);
        k_reduce<<<CROWS / 16, 256, 0, sRed>>>(y, pwt, out, c * CROWS);
    }

    cudaEventRecord(evJoin, sRed);
    cudaStreamWaitEvent(0, evJoin, 0);
}

// round 12
// speedup vs baseline: 1.3432x; 1.0731x over previous
#include <cuda_runtime.h>
#include <cuda_fp16.h>
#include <cuda.h>
#include <cstdint>

#define NB 32768
#define ND 512
#define NC 527
#define NPAD 576     // 3 * 192

#define BM 128
#define BN 192
#define BKH 64          // halfs per K-stage (128 B = one SW128 row)
#define NITK (ND / BKH) // 8
#define NCH 2
#define CRB  (NB / BM / NCH)    // 128 row-blocks per chunk
#define CROWS (NB / NCH)        // 16384 rows per chunk

#define A_BYTES (BM * 128)      // 16384
#define B_BYTES (BN * 128)      // 24576
#define STG_BYTES (A_BYTES + B_BYTES)   // 40960
#define SMEM_DYN (4 * STG_BYTES + 1024) // 164,864

// Scratch: fp16 copies of X and (padded) W, fp16 logits, tensormaps.
__device__ __half g_Xh[(size_t)NB * ND];     // 32 MB
__device__ __half g_Wh[(size_t)NPAD * ND];   // 0.56 MB (rows >= NC zeroed)
__device__ __half g_LOGH[(size_t)NB * NPAD]; // 37.7 MB
__device__ __align__(128) CUtensorMap g_tmaX;
__device__ __align__(128) CUtensorMap g_tmaW;

// ---------------------------------------------------------------------------
// K0: fp32 -> fp16 conversion (full tensors, full grid) + output zeroing
// ---------------------------------------------------------------------------
__global__ __launch_bounds__(256)
void k_conv(const float* __restrict__ X, const float* __restrict__ W,
            float* __restrict__ out) {
    if (blockIdx.x == 0 && threadIdx.x < 2) out[threadIdx.x] = 0.0f;

    const size_t stride = (size_t)gridDim.x * blockDim.x;
    size_t i0 = (size_t)blockIdx.x * blockDim.x + threadIdx.x;

    const float4* X4 = (const float4*)X;
    const size_t nx4 = (size_t)NB * ND / 4;
    for (size_t j = i0; j < nx4; j += stride) {
        float4 v = X4[j];
        __half2 h0 = __floats2half2_rn(v.x, v.y);
        __half2 h1 = __floats2half2_rn(v.z, v.w);
        uint2 p;
        p.x = *(uint32_t*)&h0; p.y = *(uint32_t*)&h1;
        *(uint2*)&g_Xh[j * 4] = p;
    }

    const size_t nw4 = (size_t)NPAD * ND / 4;
    for (size_t j = i0; j < nw4; j += stride) {
        size_t row = j >> 7;            // 128 float4 per 512-col row
        uint2 p = make_uint2(0u, 0u);
        if (row < NC) {
            float4 v = *(const float4*)&W[j * 4];
            __half2 h0 = __floats2half2_rn(v.x, v.y);
            __half2 h1 = __floats2half2_rn(v.z, v.w);
            p.x = *(uint32_t*)&h0; p.y = *(uint32_t*)&h1;
        }
        *(uint2*)&g_Wh[j * 4] = p;
    }
}

__device__ __forceinline__ void mma_f16(float* c, const uint32_t* a, const uint32_t* b) {
    asm volatile(
        "mma.sync.aligned.m16n8k16.row.col.f32.f16.f16.f32 "
        "{%0,%1,%2,%3}, {%4,%5,%6,%7}, {%8,%9}, {%0,%1,%2,%3};\n"
        : "+f"(c[0]), "+f"(c[1]), "+f"(c[2]), "+f"(c[3])
        : "r"(a[0]), "r"(a[1]), "r"(a[2]), "r"(a[3]), "r"(b[0]), "r"(b[1]));
}

__device__ __forceinline__ void ldsm_x4(uint32_t* r, uint32_t addr) {
    asm volatile("ldmatrix.sync.aligned.m8n8.x4.shared.b16 {%0,%1,%2,%3}, [%4];"
                 : "=r"(r[0]), "=r"(r[1]), "=r"(r[2]), "=r"(r[3]) : "r"(addr));
}

__device__ __forceinline__ void tma2d(uint32_t dst, const CUtensorMap* m,
                                      int cx, int cy, uint32_t mb) {
    asm volatile(
        "cp.async.bulk.tensor.2d.shared::cta.global.tile.mbarrier::complete_tx::bytes "
        "[%0], [%1, {%2, %3}], [%4];"
        :: "r"(dst), "l"(m), "r"(cx), "r"(cy), "r"(mb) : "memory");
}

__device__ __forceinline__ void mbar_wait(uint32_t addr, uint32_t parity) {
    asm volatile(
        "{\n\t.reg .pred P;\n\t"
        "W_%=:\n\t"
        "mbarrier.try_wait.parity.acquire.cta.shared::cta.b64 P, [%0], %1, 0x989680;\n\t"
        "@!P bra W_%=;\n\t}"
        :: "r"(addr), "r"(parity) : "memory");
}

#define SWZ(o) ((o) ^ (((o) >> 3) & 0x70))

// ---------------------------------------------------------------------------
// K1: fp16 mma GEMM, TMA-staged, warp-autonomous full/empty mbarrier pipeline
// (no per-stage __syncthreads). CTA 128x192, 512 thr / 16 warps (4m x 4n).
// ---------------------------------------------------------------------------
__global__ __launch_bounds__(512, 1)
void k_gemm(const float* __restrict__ bias, int rowOff) {
    extern __shared__ char dsm[];
    __shared__ float sBias[BN];
    __shared__ __align__(8) uint64_t mfull[4];
    __shared__ __align__(8) uint64_t mempty[4];

    const int tid  = threadIdx.x;
    const int lane = tid & 31;
    const int warp = tid >> 5;      // 0..15
    const int wm   = warp & 3;      // 0..3
    const int wn   = warp >> 2;     // 0..3
    const int g    = lane >> 2;     // 0..7
    const int t    = lane & 3;      // 0..3

    const int col0 = blockIdx.x * BN;
    const int row0 = rowOff + blockIdx.y * BM;

    uint32_t raw  = (uint32_t)__cvta_generic_to_shared(dsm);
    uint32_t base = (raw + 1023) & ~1023u;
    const uint32_t mf0 = (uint32_t)__cvta_generic_to_shared(&mfull[0]);
    const uint32_t me0 = (uint32_t)__cvta_generic_to_shared(&mempty[0]);

    for (int i = tid; i < BN; i += 512)
        sBias[i] = (col0 + i < NC) ? bias[col0 + i] : 0.0f;

    if (tid == 0) {
        #pragma unroll
        for (int s = 0; s < 4; s++) {
            asm volatile("mbarrier.init.shared.b64 [%0], 1;"  :: "r"(mf0 + 8 * s) : "memory");
            asm volatile("mbarrier.init.shared.b64 [%0], 16;" :: "r"(me0 + 8 * s) : "memory");
        }
        asm volatile("fence.proxy.async.shared::cta;" ::: "memory");
    }
    __syncthreads();

    auto issue = [&](int s) {       // tid 0 only
        const uint32_t dst = base + (s & 3) * STG_BYTES;
        const uint32_t mbs = mf0 + (s & 3) * 8;
        asm volatile("mbarrier.arrive.expect_tx.shared.b64 _, [%0], %1;"
                     :: "r"(mbs), "r"((uint32_t)STG_BYTES) : "memory");
        tma2d(dst,           &g_tmaX, s * BKH, row0, mbs);
        tma2d(dst + A_BYTES, &g_tmaW, s * BKH, col0, mbs);
    };

    const bool prod = (tid == 0);
    if (prod) { issue(0); issue(1); issue(2); }

    // LDSM per-lane row/column-byte offsets
    const int aRow  = (lane & 7) + ((lane >> 3) & 1) * 8;
    const int aColB = (lane >> 4) * 16;
    const int bRow  = (lane & 7) + (lane >> 4) * 8;
    const int bColB = ((lane >> 3) & 1) * 16;

    float acc[2][6][4];
    #pragma unroll
    for (int i = 0; i < 2; i++)
        #pragma unroll
        for (int j = 0; j < 6; j++)
            #pragma unroll
            for (int r = 0; r < 4; r++) acc[i][j][r] = 0.0f;

    for (int it = 0; it < NITK; it++) {
        if (prod) {
            int s = it + 3;
            if (s < NITK) {
                if (s >= 4) mbar_wait(me0 + (s & 3) * 8, 0);   // all warps done with buf
                issue(s);
            }
        }
        mbar_wait(mf0 + (it & 3) * 8, (it >> 2) & 1);

        const uint32_t sA = base + (it & 3) * STG_BYTES;
        const uint32_t sB = sA + A_BYTES;
        #pragma unroll
        for (int ks = 0; ks < 4; ks++) {           // 4 x k16 per 64-half stage
            const int kb = ks * 32;                // byte offset in 128B row
            uint32_t a[2][4], bf[3][4];
            #pragma unroll
            for (int mt = 0; mt < 2; mt++) {
                int r = wm * 32 + mt * 16 + aRow;
                uint32_t off = (uint32_t)(r * 128 + kb + aColB);
                ldsm_x4(a[mt], sA + SWZ(off));
            }
            #pragma unroll
            for (int nb = 0; nb < 3; nb++) {       // 2 n-tiles per LDSM
                int c = wn * 48 + nb * 16 + bRow;
                uint32_t off = (uint32_t)(c * 128 + kb + bColB);
                ldsm_x4(bf[nb], sB + SWZ(off));
            }
            #pragma unroll
            for (int mt = 0; mt < 2; mt++)
                #pragma unroll
                for (int nt = 0; nt < 6; nt++)
                    mma_f16(acc[mt][nt], a[mt], &bf[nt >> 1][(nt & 1) * 2]);
        }

        if (it < 4 && lane == 0)    // buffer it reused at stage it+4
            asm volatile("mbarrier.arrive.shared.b64 _, [%0];"
                         :: "r"(me0 + (it & 3) * 8) : "memory");
    }

    // epilogue: bias add + store fp16 logits
    #pragma unroll
    for (int mt = 0; mt < 2; mt++) {
        int gr = row0 + wm * 32 + mt * 16 + g;
        #pragma unroll
        for (int nt = 0; nt < 6; nt++) {
            int ci = wn * 48 + nt * 8 + 2 * t;
            float bv0 = sBias[ci], bv1 = sBias[ci + 1];
            int gc = col0 + ci;
            __half2 h0 = __floats2half2_rn(acc[mt][nt][0] + bv0, acc[mt][nt][1] + bv1);
            __half2 h1 = __floats2half2_rn(acc[mt][nt][2] + bv0, acc[mt][nt][3] + bv1);
            *(__half2*)&g_LOGH[(size_t)(gr    ) * NPAD + gc] = h0;
            *(__half2*)&g_LOGH[(size_t)(gr + 8) * NPAD + gc] = h1;
        }
    }
}

// ---------------------------------------------------------------------------
// K2: per-row BCE loss + exact top-k hit rate, one row chunk.
// fp16 logits; keys = (u16<<10) | class_index (stable-argsort tiebreak, keys
// distinct -> guaranteed early exit). One warp = 2 rows, paired-class lanes.
// ---------------------------------------------------------------------------
__global__ __launch_bounds__(256)
void k_reduce(const float* __restrict__ Y, const float* __restrict__ pw,
              float* __restrict__ out, int rowOff) {
    const int warp = threadIdx.x >> 5;
    const int lane = threadIdx.x & 31;
    const int row0 = rowOff + (blockIdx.x * 8 + warp) * 2;

    unsigned u[2][18];
    unsigned pm[2];
    int      cnt[2];
    float lsum = 0.0f;

    #pragma unroll
    for (int r = 0; r < 2; r++) {
        const __half* lg = g_LOGH + (size_t)(row0 + r) * NPAD;
        const float* yr = Y + (size_t)(row0 + r) * NC;
        unsigned m = 0;
        #pragma unroll
        for (int j = 0; j < 9; j++) {
            int c0 = 2 * lane + 64 * j;           // even; c0+1 <= 575 < NPAD
            uint32_t hp = *(const uint32_t*)&lg[c0];
            float2 zf = __half22float2(*(const __half2*)&hp);
            bool v0 = (c0 < NC), v1 = (c0 + 1 < NC);
            float y0 = 0.f, y1 = 0.f, p0 = 0.f, p1 = 0.f;
            if (v0) { y0 = yr[c0]; p0 = pw[c0]; }
            if (v1) { y1 = yr[c0 + 1]; p1 = pw[c0 + 1]; }

            float sp0 = fmaxf(zf.x, 0.f) + __logf(1.f + __expf(-fabsf(zf.x)));
            float sp1 = fmaxf(zf.y, 0.f) + __logf(1.f + __expf(-fabsf(zf.y)));
            lsum += v0 ? ((1.f + y0 * (p0 - 1.f)) * sp0 - p0 * y0 * zf.x) : 0.f;
            lsum += v1 ? ((1.f + y1 * (p1 - 1.f)) * sp1 - p1 * y1 * zf.y) : 0.f;

            m |= (y0 != 0.f) ? (1u << (2 * j)) : 0u;
            m |= (y1 != 0.f) ? (1u << (2 * j + 1)) : 0u;

            unsigned h0 = hp & 0xffffu, h1 = hp >> 16;
            unsigned u0 = (h0 & 0x8000u) ? (~h0 & 0xffffu) : (h0 | 0x8000u);
            unsigned u1 = (h1 & 0x8000u) ? (~h1 & 0xffffu) : (h1 | 0x8000u);
            u[r][2 * j]     = v0 ? ((u0 << 10) | (unsigned)c0)       : 0u;
            u[r][2 * j + 1] = v1 ? ((u1 << 10) | (unsigned)(c0 + 1)) : 0u;
        }
        pm[r]  = m;
        cnt[r] = __popc(m);
    }

    {
        int q = cnt[0] | (cnt[1] << 16);
        q = __reduce_add_sync(0xffffffffu, q);
        cnt[0] = q & 0xffff; cnt[1] = q >> 16;
    }
    #pragma unroll
    for (int o = 16; o; o >>= 1) lsum += __shfl_xor_sync(0xffffffffu, lsum, o);

    // 2-bit-per-pass radix select over 26-bit keys; exact exit at count==k.
    unsigned pre[2] = {0u, 0u};
    int done = 0;
    #pragma unroll 1
    for (int bit = 24; bit >= 0; bit -= 2) {
        const unsigned m1 = 2u << bit;
        const unsigned m0 = 1u << bit;
        int pk[2];
        #pragma unroll
        for (int r = 0; r < 2; r++) {
            const unsigned cH  = pre[r] | m1;
            const unsigned cHB = cH | m0;
            const unsigned cL  = pre[r] | m0;
            int nH = 0, nHB = 0, nL = 0;
            #pragma unroll
            for (int i = 0; i < 18; i++) {
                nH  += (u[r][i] >= cH);
                nHB += (u[r][i] >= cHB);
                nL  += (u[r][i] >= cL);
            }
            pk[r] = nH | (nHB << 10) | (nL << 20);
        }
        pk[0] = __reduce_add_sync(0xffffffffu, pk[0]);
        pk[1] = __reduce_add_sync(0xffffffffu, pk[1]);
        #pragma unroll
        for (int r = 0; r < 2; r++) {
            int nH  = pk[r] & 1023;
            int nHB = (pk[r] >> 10) & 1023;
            int nL  = (pk[r] >> 20) & 1023;
            int cur = 0x7fffffff;
            if (nHB >= cnt[r])      { pre[r] |= m1 | m0; cur = nHB; }
            else if (nH >= cnt[r])  { pre[r] |= m1;      cur = nH; }
            else if (nL >= cnt[r])  { pre[r] |= m0;      cur = nL; }
            done |= (cur == cnt[r]) << r;
        }
        if (done == 3) break;
    }

    int h0 = 0, h1 = 0;
    #pragma unroll
    for (int i = 0; i < 18; i++) {
        h0 += (((pm[0] >> i) & 1u) && (u[0][i] >= pre[0])) ? 1 : 0;
        h1 += (((pm[1] >> i) & 1u) && (u[1][i] >= pre[1])) ? 1 : 0;
    }
    int hh = h0 | (h1 << 16);
    hh = __reduce_add_sync(0xffffffffu, hh);

    if (lane == 0) {
        float sc = (float)(hh & 0xffff) / (float)cnt[0]
                 + (float)(hh >> 16)    / (float)cnt[1];
        atomicAdd(&out[0], lsum * (1.0f / ((float)NB * (float)NC)));
        atomicAdd(&out[1], sc * (1.0f / (float)NB));
    }
}

// ---------------------------------------------------------------------------
// launch: conv(+zero) -> gemm in 2 chunks; reduce chunk c overlaps gemm c+1.
// ---------------------------------------------------------------------------
typedef CUresult (*EncodeFn)(CUtensorMap*, CUtensorMapDataType, cuuint32_t, void*,
                             const cuuint64_t*, const cuuint64_t*, const cuuint32_t*,
                             const cuuint32_t*, CUtensorMapInterleave, CUtensorMapSwizzle,
                             CUtensorMapL2promotion, CUtensorMapFloatOOBfill);

extern "C" void kernel_launch(void* const* d_in, const int* in_sizes, int n_in,
                              void* d_out, int out_size) {
    const float *x = nullptr, *y = nullptr, *W = nullptr, *b = nullptr, *pwt = nullptr;
    int n527 = 0;
    for (int i = 0; i < n_in; i++) {
        if      (in_sizes[i] == NB * ND) x = (const float*)d_in[i];
        else if (in_sizes[i] == NB * NC) y = (const float*)d_in[i];
        else if (in_sizes[i] == NC * ND) W = (const float*)d_in[i];
        else if (in_sizes[i] == NC) {
            if (n527 == 0) b = (const float*)d_in[i];
            else           pwt = (const float*)d_in[i];
            n527++;
        }
    }
    float* out = (float*)d_out;

    static cudaStream_t sRed = nullptr;
    static cudaEvent_t evG[NCH], evJoin;
    static int inited = 0;
    if (!inited) {
        cudaFuncSetAttribute(k_gemm, cudaFuncAttributeMaxDynamicSharedMemorySize, SMEM_DYN);
        cudaStreamCreateWithFlags(&sRed, cudaStreamNonBlocking);
        cudaEventCreateWithFlags(&evJoin, cudaEventDisableTiming);
        for (int c = 0; c < NCH; c++)
            cudaEventCreateWithFlags(&evG[c], cudaEventDisableTiming);

        void* xh_ = nullptr; void* wh_ = nullptr;
        cudaGetSymbolAddress(&xh_, g_Xh);
        cudaGetSymbolAddress(&wh_, g_Wh);
        EncodeFn enc = nullptr;
        cudaDriverEntryPointQueryResult qres;
        cudaGetDriverEntryPoint("cuTensorMapEncodeTiled", (void**)&enc,
                                cudaEnableDefault, &qres);
        CUtensorMap hx{}, hw{};
        {
            cuuint64_t dims[2]    = {ND, NB};
            cuuint64_t strides[1] = {ND * 2};
            cuuint32_t box[2]     = {BKH, BM};
            cuuint32_t es[2]      = {1, 1};
            enc(&hx, CU_TENSOR_MAP_DATA_TYPE_FLOAT16, 2, xh_, dims, strides, box, es,
                CU_TENSOR_MAP_INTERLEAVE_NONE, CU_TENSOR_MAP_SWIZZLE_128B,
                CU_TENSOR_MAP_L2_PROMOTION_L2_128B, CU_TENSOR_MAP_FLOAT_OOB_FILL_NONE);
        }
        {
            cuuint64_t dims[2]    = {ND, NPAD};
            cuuint64_t strides[1] = {ND * 2};
            cuuint32_t box[2]     = {BKH, BN};
            cuuint32_t es[2]      = {1, 1};
            enc(&hw, CU_TENSOR_MAP_DATA_TYPE_FLOAT16, 2, wh_, dims, strides, box, es,
                CU_TENSOR_MAP_INTERLEAVE_NONE, CU_TENSOR_MAP_SWIZZLE_128B,
                CU_TENSOR_MAP_L2_PROMOTION_L2_128B, CU_TENSOR_MAP_FLOAT_OOB_FILL_NONE);
        }
        cudaMemcpyToSymbol(g_tmaX, &hx, sizeof(CUtensorMap));
        cudaMemcpyToSymbol(g_tmaW, &hw, sizeof(CUtensorMap));
        inited = 1;
    }

    k_conv<<<2048, 256>>>(x, W, out);   // also zeroes out[0..1]

    dim3 gg(NPAD / BN, CRB);            // (3, 128) per chunk
    for (int c = 0; c < NCH; c++) {
        k_gemm<<<gg, 512, SMEM_DYN>>>(b, c * CROWS);
        cudaEventRecord(evG[c], 0);
        cudaStreamWaitEvent(sRed, evG[c], 0);
        k_reduce<<<CROWS / 16, 256, 0, sRed>>>(y, pwt, out, c * CROWS);
    }

    cudaEventRecord(evJoin, sRed);
    cudaStreamWaitEvent(0, evJoin, 0);
}

// round 13
// speedup vs baseline: 1.3530x; 1.0073x over previous
#include <cuda_runtime.h>
#include <cuda_fp16.h>
#include <cuda.h>
#include <cstdint>

#define NB 32768
#define ND 512
#define NC 527
#define NPAD 576     // 3 * 192

#define BM 128
#define BN 192
#define BKH 64          // halfs per K-stage (128 B = one SW128 row)
#define NITK (ND / BKH) // 8
#define NCH 2
#define CRB  (NB / BM / NCH)    // 128 row-blocks per chunk
#define CROWS (NB / NCH)        // 16384 rows per chunk

#define A_BYTES (BM * 128)      // 16384
#define B_BYTES (BN * 128)      // 24576
#define STG_BYTES (A_BYTES + B_BYTES)   // 40960
#define SMEM_DYN (4 * STG_BYTES + 1024) // 164,864

// Scratch: fp16 copies of X and (padded) W, fp16 logits, tensormaps.
__device__ __half g_Xh[(size_t)NB * ND];     // 32 MB
__device__ __half g_Wh[(size_t)NPAD * ND];   // 0.56 MB (rows >= NC zeroed)
__device__ __half g_LOGH[(size_t)NB * NPAD]; // 37.7 MB
__device__ __align__(128) CUtensorMap g_tmaX;
__device__ __align__(128) CUtensorMap g_tmaW;

// ---------------------------------------------------------------------------
// K0: fp32 -> fp16 conversion (full tensors, full grid) + output zeroing
// ---------------------------------------------------------------------------
__global__ __launch_bounds__(256)
void k_conv(const float* __restrict__ X, const float* __restrict__ W,
            float* __restrict__ out) {
    if (blockIdx.x == 0 && threadIdx.x < 2) out[threadIdx.x] = 0.0f;

    const size_t stride = (size_t)gridDim.x * blockDim.x;
    size_t i0 = (size_t)blockIdx.x * blockDim.x + threadIdx.x;

    const float4* X4 = (const float4*)X;
    const size_t nx4 = (size_t)NB * ND / 4;
    for (size_t j = i0; j < nx4; j += stride) {
        float4 v = X4[j];
        __half2 h0 = __floats2half2_rn(v.x, v.y);
        __half2 h1 = __floats2half2_rn(v.z, v.w);
        uint2 p;
        p.x = *(uint32_t*)&h0; p.y = *(uint32_t*)&h1;
        *(uint2*)&g_Xh[j * 4] = p;
    }

    const size_t nw4 = (size_t)NPAD * ND / 4;
    for (size_t j = i0; j < nw4; j += stride) {
        size_t row = j >> 7;            // 128 float4 per 512-col row
        uint2 p = make_uint2(0u, 0u);
        if (row < NC) {
            float4 v = *(const float4*)&W[j * 4];
            __half2 h0 = __floats2half2_rn(v.x, v.y);
            __half2 h1 = __floats2half2_rn(v.z, v.w);
            p.x = *(uint32_t*)&h0; p.y = *(uint32_t*)&h1;
        }
        *(uint2*)&g_Wh[j * 4] = p;
    }
}

__device__ __forceinline__ void mma_f16(float* c, const uint32_t* a, const uint32_t* b) {
    asm volatile(
        "mma.sync.aligned.m16n8k16.row.col.f32.f16.f16.f32 "
        "{%0,%1,%2,%3}, {%4,%5,%6,%7}, {%8,%9}, {%0,%1,%2,%3};\n"
        : "+f"(c[0]), "+f"(c[1]), "+f"(c[2]), "+f"(c[3])
        : "r"(a[0]), "r"(a[1]), "r"(a[2]), "r"(a[3]), "r"(b[0]), "r"(b[1]));
}

__device__ __forceinline__ void ldsm_x4(uint32_t* r, uint32_t addr) {
    asm volatile("ldmatrix.sync.aligned.m8n8.x4.shared.b16 {%0,%1,%2,%3}, [%4];"
                 : "=r"(r[0]), "=r"(r[1]), "=r"(r[2]), "=r"(r[3]) : "r"(addr));
}

__device__ __forceinline__ void tma2d(uint32_t dst, const CUtensorMap* m,
                                      int cx, int cy, uint32_t mb) {
    asm volatile(
        "cp.async.bulk.tensor.2d.shared::cta.global.tile.mbarrier::complete_tx::bytes "
        "[%0], [%1, {%2, %3}], [%4];"
        :: "r"(dst), "l"(m), "r"(cx), "r"(cy), "r"(mb) : "memory");
}

__device__ __forceinline__ void mbar_wait(uint32_t addr, uint32_t parity) {
    asm volatile(
        "{\n\t.reg .pred P;\n\t"
        "W_%=:\n\t"
        "mbarrier.try_wait.parity.acquire.cta.shared::cta.b64 P, [%0], %1, 0x989680;\n\t"
        "@!P bra W_%=;\n\t}"
        :: "r"(addr), "r"(parity) : "memory");
}

#define SWZ(o) ((o) ^ (((o) >> 3) & 0x70))

// ---------------------------------------------------------------------------
// K1: fp16 mma GEMM, TMA-staged, warp-autonomous full/empty mbarrier pipeline.
// CTA 128x192, 256 thr / 8 warps (2m x 4n), warp tile 64x48: fragment reuse
// cuts LDSM/MMA ratio to 7/24; regs ~45K/SM leaves room for reduce overlap.
// ---------------------------------------------------------------------------
__global__ __launch_bounds__(256, 1)
void k_gemm(const float* __restrict__ bias, int rowOff) {
    extern __shared__ char dsm[];
    __shared__ float sBias[BN];
    __shared__ __align__(8) uint64_t mfull[4];
    __shared__ __align__(8) uint64_t mempty[4];

    const int tid  = threadIdx.x;
    const int lane = tid & 31;
    const int warp = tid >> 5;      // 0..7
    const int wm   = warp & 1;      // 0..1
    const int wn   = warp >> 1;     // 0..3
    const int g    = lane >> 2;     // 0..7
    const int t    = lane & 3;      // 0..3

    const int col0 = blockIdx.x * BN;
    const int row0 = rowOff + blockIdx.y * BM;

    uint32_t raw  = (uint32_t)__cvta_generic_to_shared(dsm);
    uint32_t base = (raw + 1023) & ~1023u;
    const uint32_t mf0 = (uint32_t)__cvta_generic_to_shared(&mfull[0]);
    const uint32_t me0 = (uint32_t)__cvta_generic_to_shared(&mempty[0]);

    for (int i = tid; i < BN; i += 256)
        sBias[i] = (col0 + i < NC) ? bias[col0 + i] : 0.0f;

    if (tid == 0) {
        #pragma unroll
        for (int s = 0; s < 4; s++) {
            asm volatile("mbarrier.init.shared.b64 [%0], 1;" :: "r"(mf0 + 8 * s) : "memory");
            asm volatile("mbarrier.init.shared.b64 [%0], 8;" :: "r"(me0 + 8 * s) : "memory");
        }
        asm volatile("fence.proxy.async.shared::cta;" ::: "memory");
    }
    __syncthreads();

    auto issue = [&](int s) {       // tid 0 only
        const uint32_t dst = base + (s & 3) * STG_BYTES;
        const uint32_t mbs = mf0 + (s & 3) * 8;
        asm volatile("mbarrier.arrive.expect_tx.shared.b64 _, [%0], %1;"
                     :: "r"(mbs), "r"((uint32_t)STG_BYTES) : "memory");
        tma2d(dst,           &g_tmaX, s * BKH, row0, mbs);
        tma2d(dst + A_BYTES, &g_tmaW, s * BKH, col0, mbs);
    };

    const bool prod = (tid == 0);
    if (prod) { issue(0); issue(1); issue(2); }

    // LDSM per-lane row/column-byte offsets
    const int aRow  = (lane & 7) + ((lane >> 3) & 1) * 8;
    const int aColB = (lane >> 4) * 16;
    const int bRow  = (lane & 7) + (lane >> 4) * 8;
    const int bColB = ((lane >> 3) & 1) * 16;

    float acc[4][6][4];
    #pragma unroll
    for (int i = 0; i < 4; i++)
        #pragma unroll
        for (int j = 0; j < 6; j++)
            #pragma unroll
            for (int r = 0; r < 4; r++) acc[i][j][r] = 0.0f;

    for (int it = 0; it < NITK; it++) {
        if (prod) {
            int s = it + 3;
            if (s < NITK) {
                if (s >= 4) mbar_wait(me0 + (s & 3) * 8, 0);   // all warps done with buf
                issue(s);
            }
        }
        mbar_wait(mf0 + (it & 3) * 8, (it >> 2) & 1);

        const uint32_t sA = base + (it & 3) * STG_BYTES;
        const uint32_t sB = sA + A_BYTES;
        #pragma unroll
        for (int ks = 0; ks < 4; ks++) {           // 4 x k16 per 64-half stage
            const int kb = ks * 32;                // byte offset in 128B row
            uint32_t a[4][4], bf[3][4];
            #pragma unroll
            for (int mt = 0; mt < 4; mt++) {
                int r = wm * 64 + mt * 16 + aRow;
                uint32_t off = (uint32_t)(r * 128 + kb + aColB);
                ldsm_x4(a[mt], sA + SWZ(off));
            }
            #pragma unroll
            for (int nb = 0; nb < 3; nb++) {       // 2 n-tiles per LDSM
                int c = wn * 48 + nb * 16 + bRow;
                uint32_t off = (uint32_t)(c * 128 + kb + bColB);
                ldsm_x4(bf[nb], sB + SWZ(off));
            }
            #pragma unroll
            for (int mt = 0; mt < 4; mt++)
                #pragma unroll
                for (int nt = 0; nt < 6; nt++)
                    mma_f16(acc[mt][nt], a[mt], &bf[nt >> 1][(nt & 1) * 2]);
        }

        if (it < 4 && lane == 0)    // buffer it reused at stage it+4
            asm volatile("mbarrier.arrive.shared.b64 _, [%0];"
                         :: "r"(me0 + (it & 3) * 8) : "memory");
    }

    // epilogue: bias add + store fp16 logits
    #pragma unroll
    for (int mt = 0; mt < 4; mt++) {
        int gr = row0 + wm * 64 + mt * 16 + g;
        #pragma unroll
        for (int nt = 0; nt < 6; nt++) {
            int ci = wn * 48 + nt * 8 + 2 * t;
            float bv0 = sBias[ci], bv1 = sBias[ci + 1];
            int gc = col0 + ci;
            __half2 h0 = __floats2half2_rn(acc[mt][nt][0] + bv0, acc[mt][nt][1] + bv1);
            __half2 h1 = __floats2half2_rn(acc[mt][nt][2] + bv0, acc[mt][nt][3] + bv1);
            *(__half2*)&g_LOGH[(size_t)(gr    ) * NPAD + gc] = h0;
            *(__half2*)&g_LOGH[(size_t)(gr + 8) * NPAD + gc] = h1;
        }
    }
}

// ---------------------------------------------------------------------------
// K2: per-row BCE loss + exact top-k hit rate, one row chunk. (R12 core.)
// ---------------------------------------------------------------------------
__global__ __launch_bounds__(256)
void k_reduce(const float* __restrict__ Y, const float* __restrict__ pw,
              float* __restrict__ out, int rowOff) {
    const int warp = threadIdx.x >> 5;
    const int lane = threadIdx.x & 31;
    const int row0 = rowOff + (blockIdx.x * 8 + warp) * 2;

    unsigned u[2][18];
    unsigned pm[2];
    int      cnt[2];
    float lsum = 0.0f;

    #pragma unroll
    for (int r = 0; r < 2; r++) {
        const __half* lg = g_LOGH + (size_t)(row0 + r) * NPAD;
        const float* yr = Y + (size_t)(row0 + r) * NC;
        unsigned m = 0;
        #pragma unroll
        for (int j = 0; j < 9; j++) {
            int c0 = 2 * lane + 64 * j;           // even; c0+1 <= 575 < NPAD
            uint32_t hp = *(const uint32_t*)&lg[c0];
            float2 zf = __half22float2(*(const __half2*)&hp);
            bool v0 = (c0 < NC), v1 = (c0 + 1 < NC);
            float y0 = 0.f, y1 = 0.f, p0 = 0.f, p1 = 0.f;
            if (v0) { y0 = yr[c0]; p0 = pw[c0]; }
            if (v1) { y1 = yr[c0 + 1]; p1 = pw[c0 + 1]; }

            float sp0 = fmaxf(zf.x, 0.f) + __logf(1.f + __expf(-fabsf(zf.x)));
            float sp1 = fmaxf(zf.y, 0.f) + __logf(1.f + __expf(-fabsf(zf.y)));
            lsum += v0 ? ((1.f + y0 * (p0 - 1.f)) * sp0 - p0 * y0 * zf.x) : 0.f;
            lsum += v1 ? ((1.f + y1 * (p1 - 1.f)) * sp1 - p1 * y1 * zf.y) : 0.f;

            m |= (y0 != 0.f) ? (1u << (2 * j)) : 0u;
            m |= (y1 != 0.f) ? (1u << (2 * j + 1)) : 0u;

            unsigned h0 = hp & 0xffffu, h1 = hp >> 16;
            unsigned u0 = (h0 & 0x8000u) ? (~h0 & 0xffffu) : (h0 | 0x8000u);
            unsigned u1 = (h1 & 0x8000u) ? (~h1 & 0xffffu) : (h1 | 0x8000u);
            u[r][2 * j]     = v0 ? ((u0 << 10) | (unsigned)c0)       : 0u;
            u[r][2 * j + 1] = v1 ? ((u1 << 10) | (unsigned)(c0 + 1)) : 0u;
        }
        pm[r]  = m;
        cnt[r] = __popc(m);
    }

    {
        int q = cnt[0] | (cnt[1] << 16);
        q = __reduce_add_sync(0xffffffffu, q);
        cnt[0] = q & 0xffff; cnt[1] = q >> 16;
    }
    #pragma unroll
    for (int o = 16; o; o >>= 1) lsum += __shfl_xor_sync(0xffffffffu, lsum, o);

    unsigned pre[2] = {0u, 0u};
    int done = 0;
    #pragma unroll 1
    for (int bit = 24; bit >= 0; bit -= 2) {
        const unsigned m1 = 2u << bit;
        const unsigned m0 = 1u << bit;
        int pk[2];
        #pragma unroll
        for (int r = 0; r < 2; r++) {
            const unsigned cH  = pre[r] | m1;
            const unsigned cHB = cH | m0;
            const unsigned cL  = pre[r] | m0;
            int nH = 0, nHB = 0, nL = 0;
            #pragma unroll
            for (int i = 0; i < 18; i++) {
                nH  += (u[r][i] >= cH);
                nHB += (u[r][i] >= cHB);
                nL  += (u[r][i] >= cL);
            }
            pk[r] = nH | (nHB << 10) | (nL << 20);
        }
        pk[0] = __reduce_add_sync(0xffffffffu, pk[0]);
        pk[1] = __reduce_add_sync(0xffffffffu, pk[1]);
        #pragma unroll
        for (int r = 0; r < 2; r++) {
            int nH  = pk[r] & 1023;
            int nHB = (pk[r] >> 10) & 1023;
            int nL  = (pk[r] >> 20) & 1023;
            int cur = 0x7fffffff;
            if (nHB >= cnt[r])      { pre[r] |= m1 | m0; cur = nHB; }
            else if (nH >= cnt[r])  { pre[r] |= m1;      cur = nH; }
            else if (nL >= cnt[r])  { pre[r] |= m0;      cur = nL; }
            done |= (cur == cnt[r]) << r;
        }
        if (done == 3) break;
    }

    int h0 = 0, h1 = 0;
    #pragma unroll
    for (int i = 0; i < 18; i++) {
        h0 += (((pm[0] >> i) & 1u) && (u[0][i] >= pre[0])) ? 1 : 0;
        h1 += (((pm[1] >> i) & 1u) && (u[1][i] >= pre[1])) ? 1 : 0;
    }
    int hh = h0 | (h1 << 16);
    hh = __reduce_add_sync(0xffffffffu, hh);

    if (lane == 0) {
        float sc = (float)(hh & 0xffff) / (float)cnt[0]
                 + (float)(hh >> 16)    / (float)cnt[1];
        atomicAdd(&out[0], lsum * (1.0f / ((float)NB * (float)NC)));
        atomicAdd(&out[1], sc * (1.0f / (float)NB));
    }
}

// ---------------------------------------------------------------------------
// launch: conv(+zero) -> gemm in 2 chunks; reduce chunk c overlaps gemm c+1
// (now actually co-resident: gemm 45K regs + reduce 15K < 64K regfile).
// ---------------------------------------------------------------------------
typedef CUresult (*EncodeFn)(CUtensorMap*, CUtensorMapDataType, cuuint32_t, void*,
                             const cuuint64_t*, const cuuint64_t*, const cuuint32_t*,
                             const cuuint32_t*, CUtensorMapInterleave, CUtensorMapSwizzle,
                             CUtensorMapL2promotion, CUtensorMapFloatOOBfill);

extern "C" void kernel_launch(void* const* d_in, const int* in_sizes, int n_in,
                              void* d_out, int out_size) {
    const float *x = nullptr, *y = nullptr, *W = nullptr, *b = nullptr, *pwt = nullptr;
    int n527 = 0;
    for (int i = 0; i < n_in; i++) {
        if      (in_sizes[i] == NB * ND) x = (const float*)d_in[i];
        else if (in_sizes[i] == NB * NC) y = (const float*)d_in[i];
        else if (in_sizes[i] == NC * ND) W = (const float*)d_in[i];
        else if (in_sizes[i] == NC) {
            if (n527 == 0) b = (const float*)d_in[i];
            else           pwt = (const float*)d_in[i];
            n527++;
        }
    }
    float* out = (float*)d_out;

    static cudaStream_t sRed = nullptr;
    static cudaEvent_t evG[NCH], evJoin;
    static int inited = 0;
    if (!inited) {
        cudaFuncSetAttribute(k_gemm, cudaFuncAttributeMaxDynamicSharedMemorySize, SMEM_DYN);
        cudaStreamCreateWithFlags(&sRed, cudaStreamNonBlocking);
        cudaEventCreateWithFlags(&evJoin, cudaEventDisableTiming);
        for (int c = 0; c < NCH; c++)
            cudaEventCreateWithFlags(&evG[c], cudaEventDisableTiming);

        void* xh_ = nullptr; void* wh_ = nullptr;
        cudaGetSymbolAddress(&xh_, g_Xh);
        cudaGetSymbolAddress(&wh_, g_Wh);
        EncodeFn enc = nullptr;
        cudaDriverEntryPointQueryResult qres;
        cudaGetDriverEntryPoint("cuTensorMapEncodeTiled", (void**)&enc,
                                cudaEnableDefault, &qres);
        CUtensorMap hx{}, hw{};
        {
            cuuint64_t dims[2]    = {ND, NB};
            cuuint64_t strides[1] = {ND * 2};
            cuuint32_t box[2]     = {BKH, BM};
            cuuint32_t es[2]      = {1, 1};
            enc(&hx, CU_TENSOR_MAP_DATA_TYPE_FLOAT16, 2, xh_, dims, strides, box, es,
                CU_TENSOR_MAP_INTERLEAVE_NONE, CU_TENSOR_MAP_SWIZZLE_128B,
                CU_TENSOR_MAP_L2_PROMOTION_L2_128B, CU_TENSOR_MAP_FLOAT_OOB_FILL_NONE);
        }
        {
            cuuint64_t dims[2]    = {ND, NPAD};
            cuuint64_t strides[1] = {ND * 2};
            cuuint32_t box[2]     = {BKH, BN};
            cuuint32_t es[2]      = {1, 1};
            enc(&hw, CU_TENSOR_MAP_DATA_TYPE_FLOAT16, 2, wh_, dims, strides, box, es,
                CU_TENSOR_MAP_INTERLEAVE_NONE, CU_TENSOR_MAP_SWIZZLE_128B,
                CU_TENSOR_MAP_L2_PROMOTION_L2_128B, CU_TENSOR_MAP_FLOAT_OOB_FILL_NONE);
        }
        cudaMemcpyToSymbol(g_tmaX, &hx, sizeof(CUtensorMap));
        cudaMemcpyToSymbol(g_tmaW, &hw, sizeof(CUtensorMap));
        inited = 1;
    }

    k_conv<<<2048, 256>>>(x, W, out);   // also zeroes out[0..1]

    dim3 gg(NPAD / BN, CRB);            // (3, 128) per chunk
    for (int c = 0; c < NCH; c++) {
        k_gemm<<<gg, 256, SMEM_DYN>>>(b, c * CROWS);
        cudaEventRecord(evG[c], 0);
        cudaStreamWaitEvent(sRed, evG[c], 0);
        k_reduce<<<CROWS / 16, 256, 0, sRed>>>(y, pwt, out, c * CROWS);
    }

    cudaEventRecord(evJoin, sRed);
    cudaStreamWaitEvent(0, evJoin, 0);
}

// round 14
// speedup vs baseline: 1.3885x; 1.0262x over previous
#include <cuda_runtime.h>
#include <cuda_fp16.h>
#include <cuda.h>
#include <cstdint>

#define NB 32768
#define ND 512
#define NC 527
#define NPAD 576     // 3 * 192

#define BM 128
#define BN 192
#define BKH 64          // halfs per K-stage (128 B = one SW128 row)
#define NITK (ND / BKH) // 8
#define NCH 2
#define CROWS (NB / NCH)        // 16384 rows per chunk
#define TILES ((CROWS / BM) * 3)  // 384 tiles per chunk
#define GEMM_CTAS 148

#define A_BYTES (BM * 128)      // 16384
#define B_BYTES (BN * 128)      // 24576
#define STG_BYTES (A_BYTES + B_BYTES)   // 40960
#define SMEM_DYN (4 * STG_BYTES + 1024) // 164,864

// Scratch: fp16 copies of X and (padded) W, fp16 logits, tensormaps.
__device__ __half g_Xh[(size_t)NB * ND];     // 32 MB
__device__ __half g_Wh[(size_t)NPAD * ND];   // 0.56 MB (rows >= NC zeroed)
__device__ __half g_LOGH[(size_t)NB * NPAD]; // 37.7 MB
__device__ __align__(128) CUtensorMap g_tmaX;
__device__ __align__(128) CUtensorMap g_tmaW;

// ---------------------------------------------------------------------------
// K0: fp32 -> fp16 conversion (full tensors, full grid) + output zeroing
// ---------------------------------------------------------------------------
__global__ __launch_bounds__(256)
void k_conv(const float* __restrict__ X, const float* __restrict__ W,
            float* __restrict__ out) {
    if (blockIdx.x == 0 && threadIdx.x < 2) out[threadIdx.x] = 0.0f;

    const size_t stride = (size_t)gridDim.x * blockDim.x;
    size_t i0 = (size_t)blockIdx.x * blockDim.x + threadIdx.x;

    const float4* X4 = (const float4*)X;
    const size_t nx4 = (size_t)NB * ND / 4;
    for (size_t j = i0; j < nx4; j += stride) {
        float4 v = X4[j];
        __half2 h0 = __floats2half2_rn(v.x, v.y);
        __half2 h1 = __floats2half2_rn(v.z, v.w);
        uint2 p;
        p.x = *(uint32_t*)&h0; p.y = *(uint32_t*)&h1;
        *(uint2*)&g_Xh[j * 4] = p;
    }

    const size_t nw4 = (size_t)NPAD * ND / 4;
    for (size_t j = i0; j < nw4; j += stride) {
        size_t row = j >> 7;            // 128 float4 per 512-col row
        uint2 p = make_uint2(0u, 0u);
        if (row < NC) {
            float4 v = *(const float4*)&W[j * 4];
            __half2 h0 = __floats2half2_rn(v.x, v.y);
            __half2 h1 = __floats2half2_rn(v.z, v.w);
            p.x = *(uint32_t*)&h0; p.y = *(uint32_t*)&h1;
        }
        *(uint2*)&g_Wh[j * 4] = p;
    }
}

__device__ __forceinline__ void mma_f16(float* c, const uint32_t* a, const uint32_t* b) {
    asm volatile(
        "mma.sync.aligned.m16n8k16.row.col.f32.f16.f16.f32 "
        "{%0,%1,%2,%3}, {%4,%5,%6,%7}, {%8,%9}, {%0,%1,%2,%3};\n"
        : "+f"(c[0]), "+f"(c[1]), "+f"(c[2]), "+f"(c[3])
        : "r"(a[0]), "r"(a[1]), "r"(a[2]), "r"(a[3]), "r"(b[0]), "r"(b[1]));
}

__device__ __forceinline__ void ldsm_x4(uint32_t* r, uint32_t addr) {
    asm volatile("ldmatrix.sync.aligned.m8n8.x4.shared.b16 {%0,%1,%2,%3}, [%4];"
                 : "=r"(r[0]), "=r"(r[1]), "=r"(r[2]), "=r"(r[3]) : "r"(addr));
}

__device__ __forceinline__ void tma2d(uint32_t dst, const CUtensorMap* m,
                                      int cx, int cy, uint32_t mb) {
    asm volatile(
        "cp.async.bulk.tensor.2d.shared::cta.global.tile.mbarrier::complete_tx::bytes "
        "[%0], [%1, {%2, %3}], [%4];"
        :: "r"(dst), "l"(m), "r"(cx), "r"(cy), "r"(mb) : "memory");
}

__device__ __forceinline__ void mbar_wait(uint32_t addr, uint32_t parity) {
    asm volatile(
        "{\n\t.reg .pred P;\n\t"
        "W_%=:\n\t"
        "mbarrier.try_wait.parity.acquire.cta.shared::cta.b64 P, [%0], %1, 0x989680;\n\t"
        "@!P bra W_%=;\n\t}"
        :: "r"(addr), "r"(parity) : "memory");
}

#define SWZ(o) ((o) ^ (((o) >> 3) & 0x70))

// ---------------------------------------------------------------------------
// K1: PERSISTENT fp16 mma GEMM. 148 CTAs; CTA bid owns tiles bid+148*j of the
// 384 chunk tiles. One continuous TMA ring across tiles: prefetch never
// drains at tile boundaries; ramp/epilogue amortized over 2-3 tiles.
// 8 warps (2m x 4n), warp tile 64x48.
// ---------------------------------------------------------------------------
__global__ __launch_bounds__(256, 1)
void k_gemm(const float* __restrict__ bias, int rowOff) {
    extern __shared__ char dsm[];
    __shared__ float sBias[NPAD];
    __shared__ __align__(8) uint64_t mfull[4];
    __shared__ __align__(8) uint64_t mempty[4];

    const int tid  = threadIdx.x;
    const int lane = tid & 31;
    const int warp = tid >> 5;      // 0..7
    const int wm   = warp & 1;      // 0..1
    const int wn   = warp >> 1;     // 0..3
    const int g    = lane >> 2;     // 0..7
    const int t    = lane & 3;      // 0..3
    const int bid  = blockIdx.x;

    int myT[3]; int nT = 0;
    for (int tt = bid; tt < TILES; tt += GEMM_CTAS) myT[nT++] = tt;
    const int totalG = nT * NITK;   // 16 or 24 stages

    uint32_t raw  = (uint32_t)__cvta_generic_to_shared(dsm);
    uint32_t base = (raw + 1023) & ~1023u;
    const uint32_t mf0 = (uint32_t)__cvta_generic_to_shared(&mfull[0]);
    const uint32_t me0 = (uint32_t)__cvta_generic_to_shared(&mempty[0]);

    for (int i = tid; i < NPAD; i += 256)
        sBias[i] = (i < NC) ? bias[i] : 0.0f;

    if (tid == 0) {
        #pragma unroll
        for (int s = 0; s < 4; s++) {
            asm volatile("mbarrier.init.shared.b64 [%0], 1;" :: "r"(mf0 + 8 * s) : "memory");
            asm volatile("mbarrier.init.shared.b64 [%0], 8;" :: "r"(me0 + 8 * s) : "memory");
        }
        asm volatile("fence.proxy.async.shared::cta;" ::: "memory");
    }
    __syncthreads();

    auto issue = [&](int gs) {      // tid 0 only
        const int tile = myT[gs >> 3];
        const int s    = gs & 7;
        const int b    = gs & 3;
        const uint32_t dst = base + b * STG_BYTES;
        const uint32_t mbs = mf0 + b * 8;
        asm volatile("mbarrier.arrive.expect_tx.shared.b64 _, [%0], %1;"
                     :: "r"(mbs), "r"((uint32_t)STG_BYTES) : "memory");
        tma2d(dst,           &g_tmaX, s * BKH, rowOff + (tile / 3) * BM, mbs);
        tma2d(dst + A_BYTES, &g_tmaW, s * BKH, (tile % 3) * BN,          mbs);
    };

    const bool prod = (tid == 0);
    if (prod) { issue(0); issue(1); issue(2); }

    // LDSM per-lane row/column-byte offsets
    const int aRow  = (lane & 7) + ((lane >> 3) & 1) * 8;
    const int aColB = (lane >> 4) * 16;
    const int bRow  = (lane & 7) + (lane >> 4) * 8;
    const int bColB = ((lane >> 3) & 1) * 16;

    float acc[4][6][4];
    #pragma unroll
    for (int i = 0; i < 4; i++)
        #pragma unroll
        for (int j = 0; j < 6; j++)
            #pragma unroll
            for (int r = 0; r < 4; r++) acc[i][j][r] = 0.0f;

    for (int gs = 0; gs < totalG; gs++) {
        if (prod) {
            int s = gs + 3;
            if (s < totalG) {
                // buffer s&3 last used at stage s-4; its 8 arrivals complete
                // phase round (s-4)>>2 -> wait parity ((s>>2)-1)&1
                if (s >= 4) mbar_wait(me0 + (s & 3) * 8, ((s >> 2) - 1) & 1);
                issue(s);
            }
        }
        mbar_wait(mf0 + (gs & 3) * 8, (gs >> 2) & 1);

        const uint32_t sA = base + (gs & 3) * STG_BYTES;
        const uint32_t sB = sA + A_BYTES;
        #pragma unroll
        for (int ks = 0; ks < 4; ks++) {           // 4 x k16 per 64-half stage
            const int kb = ks * 32;                // byte offset in 128B row
            uint32_t a[4][4], bf[3][4];
            #pragma unroll
            for (int mt = 0; mt < 4; mt++) {
                int r = wm * 64 + mt * 16 + aRow;
                uint32_t off = (uint32_t)(r * 128 + kb + aColB);
                ldsm_x4(a[mt], sA + SWZ(off));
            }
            #pragma unroll
            for (int nb = 0; nb < 3; nb++) {       // 2 n-tiles per LDSM
                int c = wn * 48 + nb * 16 + bRow;
                uint32_t off = (uint32_t)(c * 128 + kb + bColB);
                ldsm_x4(bf[nb], sB + SWZ(off));
            }
            #pragma unroll
            for (int mt = 0; mt < 4; mt++)
                #pragma unroll
                for (int nt = 0; nt < 6; nt++)
                    mma_f16(acc[mt][nt], a[mt], &bf[nt >> 1][(nt & 1) * 2]);
        }

        if (lane == 0)      // consumer done with buffer gs&3 (8 arrivals)
            asm volatile("mbarrier.arrive.shared.b64 _, [%0];"
                         :: "r"(me0 + (gs & 3) * 8) : "memory");

        if ((gs & 7) == 7) {
            // ---- per-tile epilogue: bias add + fp16 logits store ----
            const int tile = myT[gs >> 3];
            const int row0 = rowOff + (tile / 3) * BM;
            const int col0 = (tile % 3) * BN;
            #pragma unroll
            for (int mt = 0; mt < 4; mt++) {
                int gr = row0 + wm * 64 + mt * 16 + g;
                #pragma unroll
                for (int nt = 0; nt < 6; nt++) {
                    int ci = wn * 48 + nt * 8 + 2 * t;
                    float bv0 = sBias[col0 + ci], bv1 = sBias[col0 + ci + 1];
                    int gc = col0 + ci;
                    __half2 h0 = __floats2half2_rn(acc[mt][nt][0] + bv0, acc[mt][nt][1] + bv1);
                    __half2 h1 = __floats2half2_rn(acc[mt][nt][2] + bv0, acc[mt][nt][3] + bv1);
                    *(__half2*)&g_LOGH[(size_t)(gr    ) * NPAD + gc] = h0;
                    *(__half2*)&g_LOGH[(size_t)(gr + 8) * NPAD + gc] = h1;
                    #pragma unroll
                    for (int r = 0; r < 4; r++) acc[mt][nt][r] = 0.0f;
                }
            }
        }
    }
}

// ---------------------------------------------------------------------------
// K2: per-row BCE loss + exact top-k hit rate, one row chunk. (R12 core.)
// ---------------------------------------------------------------------------
__global__ __launch_bounds__(256)
void k_reduce(const float* __restrict__ Y, const float* __restrict__ pw,
              float* __restrict__ out, int rowOff) {
    const int warp = threadIdx.x >> 5;
    const int lane = threadIdx.x & 31;
    const int row0 = rowOff + (blockIdx.x * 8 + warp) * 2;

    unsigned u[2][18];
    unsigned pm[2];
    int      cnt[2];
    float lsum = 0.0f;

    #pragma unroll
    for (int r = 0; r < 2; r++) {
        const __half* lg = g_LOGH + (size_t)(row0 + r) * NPAD;
        const float* yr = Y + (size_t)(row0 + r) * NC;
        unsigned m = 0;
        #pragma unroll
        for (int j = 0; j < 9; j++) {
            int c0 = 2 * lane + 64 * j;           // even; c0+1 <= 575 < NPAD
            uint32_t hp = *(const uint32_t*)&lg[c0];
            float2 zf = __half22float2(*(const __half2*)&hp);
            bool v0 = (c0 < NC), v1 = (c0 + 1 < NC);
            float y0 = 0.f, y1 = 0.f, p0 = 0.f, p1 = 0.f;
            if (v0) { y0 = yr[c0]; p0 = pw[c0]; }
            if (v1) { y1 = yr[c0 + 1]; p1 = pw[c0 + 1]; }

            float sp0 = fmaxf(zf.x, 0.f) + __logf(1.f + __expf(-fabsf(zf.x)));
            float sp1 = fmaxf(zf.y, 0.f) + __logf(1.f + __expf(-fabsf(zf.y)));
            lsum += v0 ? ((1.f + y0 * (p0 - 1.f)) * sp0 - p0 * y0 * zf.x) : 0.f;
            lsum += v1 ? ((1.f + y1 * (p1 - 1.f)) * sp1 - p1 * y1 * zf.y) : 0.f;

            m |= (y0 != 0.f) ? (1u << (2 * j)) : 0u;
            m |= (y1 != 0.f) ? (1u << (2 * j + 1)) : 0u;

            unsigned h0 = hp & 0xffffu, h1 = hp >> 16;
            unsigned u0 = (h0 & 0x8000u) ? (~h0 & 0xffffu) : (h0 | 0x8000u);
            unsigned u1 = (h1 & 0x8000u) ? (~h1 & 0xffffu) : (h1 | 0x8000u);
            u[r][2 * j]     = v0 ? ((u0 << 10) | (unsigned)c0)       : 0u;
            u[r][2 * j + 1] = v1 ? ((u1 << 10) | (unsigned)(c0 + 1)) : 0u;
        }
        pm[r]  = m;
        cnt[r] = __popc(m);
    }

    {
        int q = cnt[0] | (cnt[1] << 16);
        q = __reduce_add_sync(0xffffffffu, q);
        cnt[0] = q & 0xffff; cnt[1] = q >> 16;
    }
    #pragma unroll
    for (int o = 16; o; o >>= 1) lsum += __shfl_xor_sync(0xffffffffu, lsum, o);

    unsigned pre[2] = {0u, 0u};
    int done = 0;
    #pragma unroll 1
    for (int bit = 24; bit >= 0; bit -= 2) {
        const unsigned m1 = 2u << bit;
        const unsigned m0 = 1u << bit;
        int pk[2];
        #pragma unroll
        for (int r = 0; r < 2; r++) {
            const unsigned cH  = pre[r] | m1;
            const unsigned cHB = cH | m0;
            const unsigned cL  = pre[r] | m0;
            int nH = 0, nHB = 0, nL = 0;
            #pragma unroll
            for (int i = 0; i < 18; i++) {
                nH  += (u[r][i] >= cH);
                nHB += (u[r][i] >= cHB);
                nL  += (u[r][i] >= cL);
            }
            pk[r] = nH | (nHB << 10) | (nL << 20);
        }
        pk[0] = __reduce_add_sync(0xffffffffu, pk[0]);
        pk[1] = __reduce_add_sync(0xffffffffu, pk[1]);
        #pragma unroll
        for (int r = 0; r < 2; r++) {
            int nH  = pk[r] & 1023;
            int nHB = (pk[r] >> 10) & 1023;
            int nL  = (pk[r] >> 20) & 1023;
            int cur = 0x7fffffff;
            if (nHB >= cnt[r])      { pre[r] |= m1 | m0; cur = nHB; }
            else if (nH >= cnt[r])  { pre[r] |= m1;      cur = nH; }
            else if (nL >= cnt[r])  { pre[r] |= m0;      cur = nL; }
            done |= (cur == cnt[r]) << r;
        }
        if (done == 3) break;
    }

    int h0 = 0, h1 = 0;
    #pragma unroll
    for (int i = 0; i < 18; i++) {
        h0 += (((pm[0] >> i) & 1u) && (u[0][i] >= pre[0])) ? 1 : 0;
        h1 += (((pm[1] >> i) & 1u) && (u[1][i] >= pre[1])) ? 1 : 0;
    }
    int hh = h0 | (h1 << 16);
    hh = __reduce_add_sync(0xffffffffu, hh);

    if (lane == 0) {
        float sc = (float)(hh & 0xffff) / (float)cnt[0]
                 + (float)(hh >> 16)    / (float)cnt[1];
        atomicAdd(&out[0], lsum * (1.0f / ((float)NB * (float)NC)));
        atomicAdd(&out[1], sc * (1.0f / (float)NB));
    }
}

// ---------------------------------------------------------------------------
// launch: conv(+zero) -> persistent gemm in 2 chunks; reduce chunk c on a
// second stream after gemm chunk c.
// ---------------------------------------------------------------------------
typedef CUresult (*EncodeFn)(CUtensorMap*, CUtensorMapDataType, cuuint32_t, void*,
                             const cuuint64_t*, const cuuint64_t*, const cuuint32_t*,
                             const cuuint32_t*, CUtensorMapInterleave, CUtensorMapSwizzle,
                             CUtensorMapL2promotion, CUtensorMapFloatOOBfill);

extern "C" void kernel_launch(void* const* d_in, const int* in_sizes, int n_in,
                              void* d_out, int out_size) {
    const float *x = nullptr, *y = nullptr, *W = nullptr, *b = nullptr, *pwt = nullptr;
    int n527 = 0;
    for (int i = 0; i < n_in; i++) {
        if      (in_sizes[i] == NB * ND) x = (const float*)d_in[i];
        else if (in_sizes[i] == NB * NC) y = (const float*)d_in[i];
        else if (in_sizes[i] == NC * ND) W = (const float*)d_in[i];
        else if (in_sizes[i] == NC) {
            if (n527 == 0) b = (const float*)d_in[i];
            else           pwt = (const float*)d_in[i];
            n527++;
        }
    }
    float* out = (float*)d_out;

    static cudaStream_t sRed = nullptr;
    static cudaEvent_t evG[NCH], evJoin;
    static int inited = 0;
    if (!inited) {
        cudaFuncSetAttribute(k_gemm, cudaFuncAttributeMaxDynamicSharedMemorySize, SMEM_DYN);
        cudaStreamCreateWithFlags(&sRed, cudaStreamNonBlocking);
        cudaEventCreateWithFlags(&evJoin, cudaEventDisableTiming);
        for (int c = 0; c < NCH; c++)
            cudaEventCreateWithFlags(&evG[c], cudaEventDisableTiming);

        void* xh_ = nullptr; void* wh_ = nullptr;
        cudaGetSymbolAddress(&xh_, g_Xh);
        cudaGetSymbolAddress(&wh_, g_Wh);
        EncodeFn enc = nullptr;
        cudaDriverEntryPointQueryResult qres;
        cudaGetDriverEntryPoint("cuTensorMapEncodeTiled", (void**)&enc,
                                cudaEnableDefault, &qres);
        CUtensorMap hx{}, hw{};
        {
            cuuint64_t dims[2]    = {ND, NB};
            cuuint64_t strides[1] = {ND * 2};
            cuuint32_t box[2]     = {BKH, BM};
            cuuint32_t es[2]      = {1, 1};
            enc(&hx, CU_TENSOR_MAP_DATA_TYPE_FLOAT16, 2, xh_, dims, strides, box, es,
                CU_TENSOR_MAP_INTERLEAVE_NONE, CU_TENSOR_MAP_SWIZZLE_128B,
                CU_TENSOR_MAP_L2_PROMOTION_L2_128B, CU_TENSOR_MAP_FLOAT_OOB_FILL_NONE);
        }
        {
            cuuint64_t dims[2]    = {ND, NPAD};
            cuuint64_t strides[1] = {ND * 2};
            cuuint32_t box[2]     = {BKH, BN};
            cuuint32_t es[2]      = {1, 1};
            enc(&hw, CU_TENSOR_MAP_DATA_TYPE_FLOAT16, 2, wh_, dims, strides, box, es,
                CU_TENSOR_MAP_INTERLEAVE_NONE, CU_TENSOR_MAP_SWIZZLE_128B,
                CU_TENSOR_MAP_L2_PROMOTION_L2_128B, CU_TENSOR_MAP_FLOAT_OOB_FILL_NONE);
        }
        cudaMemcpyToSymbol(g_tmaX, &hx, sizeof(CUtensorMap));
        cudaMemcpyToSymbol(g_tmaW, &hw, sizeof(CUtensorMap));
        inited = 1;
    }

    k_conv<<<2048, 256>>>(x, W, out);   // also zeroes out[0..1]

    for (int c = 0; c < NCH; c++) {
        k_gemm<<<GEMM_CTAS, 256, SMEM_DYN>>>(b, c * CROWS);
        cudaEventRecord(evG[c], 0);
        cudaStreamWaitEvent(sRed, evG[c], 0);
        k_reduce<<<CROWS / 16, 256, 0, sRed>>>(y, pwt, out, c * CROWS);
    }

    cudaEventRecord(evJoin, sRed);
    cudaStreamWaitEvent(0, evJoin, 0);
}